// round 8
// baseline (speedup 1.0000x reference)
#include <cuda_runtime.h>
#include <cuda_bf16.h>
#include <math.h>
#include <stdint.h>

#define BB   8192
#define MM   10
#define NNB  9
#define FIN  128
#define DXX  128
#define KK   64
#define LL   32
#define NALL 100000
#define GN   192
#define TB2  16

// ------------------- device scratch -------------------
__device__ float g_tnxT[FIN*LL];
__device__ float g_tnsT[NNB*LL];
__device__ float g_Bmat[FIN*GN];
__device__ float g_biasv[GN];
__device__ float g_cSg[64];
__device__ float g_cCb[64];
__device__ float g_Hraw[(size_t)BB*MM*GN];
__device__ float g_HrawP[640*GN];
__device__ __align__(16) __nv_bfloat16 g_BtileH[2*GN*136];   // [half][n][k_pad136]

__device__ float g_hproto_root[KK*DXX];
__device__ float g_hproto_sq[KK];
__device__ float g_hp[KK*32];
__device__ float g_Pfeat[KK*576];
__device__ float g_Pstr[KK*576];
__device__ float g_Prad[KK*18];

__device__ float g_hroot[BB*DXX];
__device__ float g_hrootsq[BB];
__device__ float g_hb[BB*32];
__device__ float g_alpha[BB];
__device__ float g_Afeat[(size_t)BB*576];
__device__ float g_T1feat[BB];
__device__ float g_Astr[(size_t)BB*576];
__device__ float g_T1str[BB];
__device__ float g_Arad[BB*18];
__device__ float g_Srad[BB];

// ------------------- register-resident 9-input sorting networks -------------------
// classic 25-comparator network: sort triples, sort triple-columns, merge.
#define NET9_APPLY(CE) \
  CE(0,1) CE(3,4) CE(6,7) CE(1,2) CE(4,5) CE(7,8) CE(0,1) CE(3,4) CE(6,7) \
  CE(0,3) CE(3,6) CE(0,3) CE(1,4) CE(4,7) CE(1,4) CE(2,5) CE(5,8) CE(2,5) \
  CE(1,3) CE(5,7) CE(2,6) CE(4,6) CE(2,4) CE(2,3) CE(5,6)

__device__ __forceinline__ void net_sort9(float* v){
#define CE_S(i,j) { float a=v[i], b=v[j]; v[i]=fminf(a,b); v[j]=fmaxf(a,b); }
  NET9_APPLY(CE_S)
#undef CE_S
}
// stable argsort: lexicographic (value, original index) — total order, so the
// network output equals jnp.argsort's stable ascending order.
__device__ __forceinline__ void net_argsort9(float* v, int* id){
#define CE_A(i,j) { float vi=v[i], vj=v[j]; int ii=id[i], ij=id[j]; \
  bool sw = (vi>vj) || ((vi==vj) && (ii>ij)); \
  v[i]=sw?vj:vi; v[j]=sw?vi:vj; id[i]=sw?ij:ii; id[j]=sw?ii:ij; }
  NET9_APPLY(CE_A)
#undef CE_A
}

__device__ __forceinline__ float wredsum(float v){
  #pragma unroll
  for (int o=16;o;o>>=1) v += __shfl_xor_sync(0xffffffffu, v, o);
  return v;
}
__device__ __forceinline__ uint32_t smem_u32(const void* p){
  uint32_t a;
  asm("{ .reg .u64 t; cvta.to.shared.u64 t, %1; cvt.u32.u64 %0, t; }" : "=r"(a) : "l"(p));
  return a;
}
// ---- sm_80-compatible tensor core ops ----
__device__ __forceinline__ void ldsm_x4(uint32_t* r, uint32_t addr){
  asm volatile("ldmatrix.sync.aligned.m8n8.x4.shared.b16 {%0,%1,%2,%3}, [%4];"
    : "=r"(r[0]),"=r"(r[1]),"=r"(r[2]),"=r"(r[3]) : "r"(addr));
}
__device__ __forceinline__ void ldsm_x2(uint32_t* r, uint32_t addr){
  asm volatile("ldmatrix.sync.aligned.m8n8.x2.shared.b16 {%0,%1}, [%2];"
    : "=r"(r[0]),"=r"(r[1]) : "r"(addr));
}
__device__ __forceinline__ void mma16816(float* c, const uint32_t* a, const uint32_t* b){
  asm volatile(
    "mma.sync.aligned.m16n8k16.row.col.f32.bf16.bf16.f32 "
    "{%0,%1,%2,%3}, {%4,%5,%6,%7}, {%8,%9}, {%0,%1,%2,%3};"
    : "+f"(c[0]),"+f"(c[1]),"+f"(c[2]),"+f"(c[3])
    : "r"(a[0]),"r"(a[1]),"r"(a[2]),"r"(a[3]), "r"(b[0]),"r"(b[1]));
}

// ------------------- kernel 0: normalize thetas -------------------
__global__ void k_tn(const float* theta_x, const float* theta_s){
  int t = threadIdx.x, w=t>>5, lane=t&31;
  for (int row=w; row<LL; row+=4){
    float s=0.f;
    for (int j=lane;j<FIN;j+=32){ float v=theta_x[row*FIN+j]; s+=v*v; }
    s = wredsum(s);
    float inv = 1.0f/sqrtf(s);
    for (int j=lane;j<FIN;j+=32) g_tnxT[j*LL+row] = theta_x[row*FIN+j]*inv;
  }
  if (t < LL){
    float s=0.f;
    for (int j=0;j<NNB;j++){ float v=theta_s[t*NNB+j]; s+=v*v; }
    float inv = 1.0f/sqrtf(s);
    for (int j=0;j<NNB;j++) g_tnsT[j*LL+t] = theta_s[t*NNB+j]*inv;
  }
}

// ------------------- kernel 0b: build folded B matrix -------------------
__global__ void k_prep(const float* Wlin, const float* blin,
                       const float* lng, const float* lnb,
                       const float* an_w1){
  int bid = blockIdx.x, t = threadIdx.x;
  if (bid < 32){
    int out = bid*256 + t;
    int i = out >> 6, c = out & 63;
    float acc = 0.f;
    for (int d=0; d<FIN; d++){
      float th = (c<32) ? g_tnxT[d*LL + c] : an_w1[d*32 + (c-32)];
      acc += Wlin[i*DXX + d] * (lng[d]*th);
    }
    g_Bmat[i*GN + 128 + c] = acc;
  } else if (bid < 40){
    int base = (bid-32)*2048;
    for (int it=0; it<8; it++){
      int u = base + t + it*256;
      g_Bmat[(u>>7)*GN + (u&127)] = Wlin[u];
    }
  } else {
    if (t < 128) g_biasv[t] = blin[t];
    if (t < 64){
      float bs=0.f, sg=0.f, cb=0.f;
      for (int d=0; d<FIN; d++){
        float th = (t<32) ? g_tnxT[d*LL + t] : an_w1[d*32 + (t-32)];
        float v = lng[d]*th;
        bs += blin[d]*v;
        sg += v;
        cb += lnb[d]*th;
      }
      g_biasv[128+t]=bs; g_cSg[t]=sg; g_cCb[t]=cb;
    }
  }
}

// ------------------- kernel 0c: bf16 hi/lo padded B tiles [half][n][136] -------------------
__global__ void k_prepB(){
  int e = blockIdx.x*256 + threadIdx.x;     // < 49152 = 2*192*128
  int half = e / 24576;
  int r = e % 24576;
  int n = r >> 7, k = r & 127;
  float v = g_Bmat[k*GN + n];
  __nv_bfloat16 hb = __float2bfloat16(v);
  __nv_bfloat16 val = (half==0) ? hb : __float2bfloat16(v - __bfloat162float(hb));
  g_BtileH[(half*GN + n)*136 + k] = val;
}

// ------------------- kernel 2a: split-bf16 mma.sync gathered GEMM -------------------
// blocks [0,640): batch rows -> g_Hraw ; blocks [640,645): proto rows -> g_HrawP
#define SM_IDX   0
#define SM_BIAS  512
#define SM_AHI   2048
#define SM_ALO   (SM_AHI + 128*136*2)
#define SM_BHI   (SM_ALO + 128*136*2)
#define SM_BLO   (SM_BHI + 192*136*2)
#define SMEM_LIN (SM_BLO + 192*136*2)      // 176128 bytes
#define STG_STRIDE 196

__global__ __launch_bounds__(256)
void k_lin_mma(const float* features, const int* idxs,
               const float* proto_root, const float* proto_neigh)
{
  extern __shared__ char smem[];
  int tid = threadIdx.x;
  int wid = tid >> 5, lane = tid & 31;
  bool isProto = (blockIdx.x >= 640);
  size_t row0 = (size_t)blockIdx.x * 128;
  int prow0 = (blockIdx.x - 640) * 128;
  int* sIdx = (int*)(smem + SM_IDX);
  float* sBias = (float*)(smem + SM_BIAS);

  if (!isProto && tid < 128) sIdx[tid] = idxs[row0 + tid];
  if (tid < 192) sBias[tid] = g_biasv[tid];

  {
    const uint4* src = (const uint4*)g_BtileH;
    uint4* dst = (uint4*)(smem + SM_BHI);
    #pragma unroll
    for (int i=0;i<26;i++){
      int u = tid + i*256;
      if (u < 6528) dst[u] = src[u];
    }
  }
  __syncthreads();

  // A gather + hi/lo split into padded [128][136] bf16 tiles
  #pragma unroll
  for (int i=0;i<16;i++){
    int u = tid + i*256;             // 0..4095 = 128 rows x 32 float4
    int row = u >> 5, q = u & 31;
    float4 v;
    if (!isProto){
      int id = sIdx[row];
      if (id == NALL) v = make_float4(0.f,0.f,0.f,0.f);
      else v = *(const float4*)&features[(size_t)id*FIN + q*4];
    } else {
      int pr = prow0 + row;
      int k = pr/10, m = pr%10;
      const float* src = (m==0) ? (proto_root + (size_t)k*FIN)
                                : (proto_neigh + ((size_t)k*NNB + (m-1))*FIN);
      v = *(const float4*)&src[q*4];
    }
    __nv_bfloat162 h01 = __floats2bfloat162_rn(v.x, v.y);
    __nv_bfloat162 h23 = __floats2bfloat162_rn(v.z, v.w);
    float2 f01 = __bfloat1622float2(h01);
    float2 f23 = __bfloat1622float2(h23);
    __nv_bfloat162 l01 = __floats2bfloat162_rn(v.x - f01.x, v.y - f01.y);
    __nv_bfloat162 l23 = __floats2bfloat162_rn(v.z - f23.x, v.w - f23.y);
    uint32_t off = (uint32_t)(row*136 + q*4)*2;
    *(__nv_bfloat162*)(smem + SM_AHI + off)     = h01;
    *(__nv_bfloat162*)(smem + SM_AHI + off + 4) = h23;
    *(__nv_bfloat162*)(smem + SM_ALO + off)     = l01;
    *(__nv_bfloat162*)(smem + SM_ALO + off + 4) = l23;
  }
  __syncthreads();

  int wm = wid >> 1, wn = wid & 1;
  int mbase = wm*32, nbase = wn*96;
  uint32_t sb = smem_u32(smem);

  float acc[2][12][4];
  #pragma unroll
  for (int mt=0;mt<2;mt++)
    #pragma unroll
    for (int j=0;j<12;j++)
      #pragma unroll
      for (int q=0;q<4;q++) acc[mt][j][q]=0.f;

  int aRow = mbase + ((lane>>3)&1)*8 + (lane&7);
  int aK   = (lane>>4)*8;
  int bRow = nbase + (lane&7);
  int bK   = ((lane>>3)&1)*8;

  #pragma unroll
  for (int kc=0; kc<8; kc++){
    uint32_t bf[12][2];
    #pragma unroll
    for (int j=0;j<12;j++)
      ldsm_x2(bf[j], sb + SM_BHI + (uint32_t)((bRow + j*8)*136 + kc*16 + bK)*2);
    uint32_t af[2][4];
    #pragma unroll
    for (int mt=0;mt<2;mt++)
      ldsm_x4(af[mt], sb + SM_AHI + (uint32_t)((aRow + mt*16)*136 + kc*16 + aK)*2);
    #pragma unroll
    for (int mt=0;mt<2;mt++)
      #pragma unroll
      for (int j=0;j<12;j++) mma16816(acc[mt][j], af[mt], bf[j]);
    #pragma unroll
    for (int mt=0;mt<2;mt++)
      ldsm_x4(af[mt], sb + SM_ALO + (uint32_t)((aRow + mt*16)*136 + kc*16 + aK)*2);
    #pragma unroll
    for (int mt=0;mt<2;mt++)
      #pragma unroll
      for (int j=0;j<12;j++) mma16816(acc[mt][j], af[mt], bf[j]);
  }
  #pragma unroll
  for (int kc=0; kc<8; kc++){
    uint32_t bf[12][2];
    #pragma unroll
    for (int j=0;j<12;j++)
      ldsm_x2(bf[j], sb + SM_BLO + (uint32_t)((bRow + j*8)*136 + kc*16 + bK)*2);
    uint32_t af[2][4];
    #pragma unroll
    for (int mt=0;mt<2;mt++)
      ldsm_x4(af[mt], sb + SM_AHI + (uint32_t)((aRow + mt*16)*136 + kc*16 + aK)*2);
    #pragma unroll
    for (int mt=0;mt<2;mt++)
      #pragma unroll
      for (int j=0;j<12;j++) mma16816(acc[mt][j], af[mt], bf[j]);
  }
  __syncthreads();

  float* stage = (float*)(smem + SM_AHI);
  {
    int r = lane >> 2, c2 = 2*(lane & 3);
    #pragma unroll
    for (int mt=0;mt<2;mt++){
      int rr = mbase + mt*16 + r;
      #pragma unroll
      for (int j=0;j<12;j++){
        int cc = nbase + j*8 + c2;
        float b0 = sBias[cc], b1 = sBias[cc+1];
        *(float2*)&stage[rr*STG_STRIDE + cc]     = make_float2(acc[mt][j][0]+b0, acc[mt][j][1]+b1);
        *(float2*)&stage[(rr+8)*STG_STRIDE + cc] = make_float2(acc[mt][j][2]+b0, acc[mt][j][3]+b1);
      }
    }
  }
  __syncthreads();
  #pragma unroll
  for (int i=0;i<24;i++){
    int u = tid + i*256;                 // 128 rows x 48 float4
    int row = u/48, q = u%48;
    float4 val = *(float4*)&stage[row*STG_STRIDE + q*4];
    if (!isProto) *(float4*)&g_Hraw[(row0 + row)*GN + q*4] = val;
    else          *(float4*)&g_HrawP[(size_t)(prow0 + row)*GN + q*4] = val;
  }
}

// ------------------- kernel 1 v2: warp-per-k proto lite (grid=8, block=256) -------------------
__global__ __launch_bounds__(256)
void k_proto_lite(const float* lng, const float* lnb,
                  const float* sg, const float* sb,
                  const float* wn_w1, const float* proto_rad, const float* proto_dn)
{
  int tid = threadIdx.x;
  int w = tid >> 5, lane = tid & 31;
  int k = blockIdx.x*8 + w;

  __shared__ float sHn[8][FIN];
  __shared__ float sC[8][NNB][NNB];
  __shared__ float sTnsT[NNB][32];
  for (int u=tid; u<NNB*32; u+=256) sTnsT[u>>5][u&31] = g_tnsT[u];
  __syncthreads();

  const float* HP = g_HrawP + (size_t)k*MM*GN;

  // LN row0 -> hproto_root, hproto_sq, sHn
  float lg0=lng[lane], lg1=lng[lane+32], lg2=lng[lane+64], lg3=lng[lane+96];
  float lb0=lnb[lane], lb1=lnb[lane+32], lb2=lnb[lane+64], lb3=lnb[lane+96];
  {
    float a0=HP[lane], a1=HP[lane+32], a2=HP[lane+64], a3=HP[lane+96];
    float s = wredsum(a0+a1+a2+a3);
    float mu = s*(1.f/FIN);
    float d0=a0-mu,d1=a1-mu,d2=a2-mu,d3=a3-mu;
    float s2 = wredsum(d0*d0+d1*d1+d2*d2+d3*d3);
    float rs = rsqrtf(s2*(1.f/FIN)+1e-5f);
    float h0=d0*rs*lg0+lb0, h1=d1*rs*lg1+lb1, h2=d2*rs*lg2+lb2, h3=d3*rs*lg3+lb3;
    sHn[w][lane]=h0; sHn[w][lane+32]=h1; sHn[w][lane+64]=h2; sHn[w][lane+96]=h3;
    g_hproto_root[k*DXX+lane]=h0; g_hproto_root[k*DXX+lane+32]=h1;
    g_hproto_root[k*DXX+lane+64]=h2; g_hproto_root[k*DXX+lane+96]=h3;
    float qq = wredsum(h0*h0+h1*h1+h2*h2+h3*h3);
    if (lane==0) g_hproto_sq[k]=qq;
  }
  float muv[NNB], rsv[NNB];
  #pragma unroll
  for (int r=1; r<MM; r++){
    const float* Hr = HP + r*GN;
    float a0=Hr[lane], a1=Hr[lane+32], a2=Hr[lane+64], a3=Hr[lane+96];
    float s = wredsum(a0+a1+a2+a3);
    float mu = s*(1.f/FIN);
    float d0=a0-mu,d1=a1-mu,d2=a2-mu,d3=a3-mu;
    float s2 = wredsum(d0*d0+d1*d1+d2*d2+d3*d3);
    muv[r-1]=mu; rsv[r-1]=rsqrtf(s2*(1.f/FIN)+1e-5f);
  }
  __syncwarp();
  // hp = h_root @ wn_w1[DX:]
  {
    float v=0.f;
    #pragma unroll 8
    for (int d=0; d<DXX; d++) v += sHn[w][d]*wn_w1[(DXX+d)*32+lane];
    g_hp[k*32+lane]=v;
  }
  // feat P: folded projection + sort
  {
    float cSgl=g_cSg[lane], cCbl=g_cCb[lane];
    float pv[NNB];
    #pragma unroll
    for (int m=0;m<NNB;m++)
      pv[m] = rsv[m]*(HP[(1+m)*GN+128+lane] - muv[m]*cSgl) + cCbl;
    net_sort9(pv);
    #pragma unroll
    for (int j=0;j<NNB;j++){
      g_Pfeat[k*576 + j*LL + lane]       = pv[j];
      g_Pfeat[k*576 + 288 + j*LL + lane] = pv[j]*pv[j];
    }
  }
  // C build
  if (lane < 36){
    int p=lane, i=0;
    while (p >= NNB-1-i){ p -= NNB-1-i; i++; }
    int j = i+1+p;
    float x = proto_dn[lane*KK + k];
    float s = 1.0f/(1.0f+expf(-x));
    sC[w][i][j]=s; sC[w][j][i]=s;
  }
  if (lane < NNB) sC[w][lane][lane]=0.f;
  __syncwarp();
  // column sort (in place, each lane owns one column)
  if (lane < NNB){
    float c[NNB];
    #pragma unroll
    for (int i=0;i<NNB;i++) c[i]=sC[w][i][lane];
    net_sort9(c);
    #pragma unroll
    for (int i=0;i<NNB;i++) sC[w][i][lane]=c[i];
  }
  __syncwarp();
  // row LN
  if (lane < NNB){
    float mu=0.f;
    #pragma unroll
    for (int j=0;j<NNB;j++) mu+=sC[w][lane][j];
    mu *= (1.f/NNB);
    float var=0.f;
    #pragma unroll
    for (int j=0;j<NNB;j++){ float d=sC[w][lane][j]-mu; var+=d*d; }
    var *= (1.f/NNB);
    float rstd=rsqrtf(var+1e-5f);
    #pragma unroll
    for (int j=0;j<NNB;j++) sC[w][lane][j]=(sC[w][lane][j]-mu)*rstd*sg[j]+sb[j];
  }
  __syncwarp();
  // str P: projection + sort
  {
    float pv[NNB];
    #pragma unroll
    for (int m=0;m<NNB;m++){
      float v2=0.f;
      #pragma unroll
      for (int j=0;j<NNB;j++) v2 += sC[w][m][j]*sTnsT[j][lane];
      pv[m]=v2;
    }
    net_sort9(pv);
    #pragma unroll
    for (int j=0;j<NNB;j++){
      g_Pstr[k*576 + j*LL + lane]       = pv[j];
      g_Pstr[k*576 + 288 + j*LL + lane] = pv[j]*pv[j];
    }
  }
  // rad
  if (lane==0){
    float r[NNB];
    #pragma unroll
    for (int j=0;j<NNB;j++) r[j]=proto_rad[k*NNB+j];
    net_sort9(r);
    #pragma unroll
    for (int j=0;j<NNB;j++){ g_Prad[k*18+j]=r[j]; g_Prad[k*18+9+j]=r[j]*r[j]; }
  }
}

// ------------------- kernel 2b: warp-per-b light pass (grid=BB/8, block=256) -------------------
__global__ __launch_bounds__(256)
void k_phase1b(const float* adj, const int* idxs,
               const float* lng, const float* lnb,
               const float* sg, const float* sb,
               const float* an_b1, const float* an_w2, const float* an_b2,
               const float* wn_w1, const float* wn_b1,
               const float* alpha_raw)
{
  int tid = threadIdx.x;
  int w = tid >> 5, lane = tid & 31;
  int b = blockIdx.x*8 + w;

  __shared__ float sDm[8][MM][MM];
  __shared__ float sHS[8][NNB][NNB];
  __shared__ float sHn[8][FIN];
  __shared__ float sVm[8][NNB];
  __shared__ unsigned sNbr[8][MM];
  __shared__ float sTnsT[NNB][32];

  for (int u=tid; u<NNB*32; u+=256) sTnsT[u>>5][u&31] = g_tnsT[u];

  const float* HR = g_Hraw + (size_t)b*MM*GN;

  if (lane < MM){
    int idv = idxs[b*MM + lane];
    if (lane >= 1) sVm[w][lane-1] = (idv != NALL) ? 1.f : 0.f;
    unsigned nb=0;
    const float* arow = adj + (size_t)b*MM*MM + lane*MM;
    #pragma unroll
    for (int j=0;j<MM;j++) if (arow[j] > 1e-5f) nb |= (1u<<j);
    sNbr[w][lane]=nb;
  }
  __syncthreads();

  float vs = 0.f;
  #pragma unroll
  for (int j=0;j<NNB;j++) vs += sVm[w][j];
  float vsi = 1.f/(vs + 1e-9f);

  if (lane < MM){
    float drow[MM];
    #pragma unroll
    for (int j=0;j<MM;j++) drow[j] = (j==lane)?0.f:10.f;
    unsigned reach = 1u<<lane, frontier = 1u<<lane;
    for (int step=1; step<MM; step++){
      unsigned nxt=0;
      #pragma unroll
      for (int v=0;v<MM;v++) if (frontier & (1u<<v)) nxt |= sNbr[w][v];
      nxt &= ~reach;
      if (!nxt) break;
      #pragma unroll
      for (int v=0;v<MM;v++) if (nxt & (1u<<v)) drow[v]=(float)step;
      reach |= nxt; frontier = nxt;
    }
    #pragma unroll
    for (int j=0;j<MM;j++) sDm[w][lane][j]=drow[j];
  }
  __syncwarp();
  for (int q=lane; q<MM*MM; q+=32){
    int i=q/MM, j=q%MM;
    float fi = (i==0)?1.f:sVm[w][i-1];
    float fj = (j==0)?1.f:sVm[w][j-1];
    sDm[w][i][j] = (fi*fj>0.f) ? sDm[w][i][j]*0.1f : 1.0f;
  }
  __syncwarp();

  float lg0=lng[lane], lg1=lng[lane+32], lg2=lng[lane+64], lg3=lng[lane+96];
  float lb0=lnb[lane], lb1=lnb[lane+32], lb2=lnb[lane+64], lb3=lnb[lane+96];
  {
    float a0=HR[lane], a1=HR[lane+32], a2=HR[lane+64], a3=HR[lane+96];
    float s = wredsum(a0+a1+a2+a3);
    float mu = s*(1.f/FIN);
    float d0=a0-mu,d1=a1-mu,d2=a2-mu,d3=a3-mu;
    float s2 = wredsum(d0*d0+d1*d1+d2*d2+d3*d3);
    float rs = rsqrtf(s2*(1.f/FIN)+1e-5f);
    float h0=d0*rs*lg0+lb0, h1=d1*rs*lg1+lb1, h2=d2*rs*lg2+lb2, h3=d3*rs*lg3+lb3;
    sHn[w][lane]=h0; sHn[w][lane+32]=h1; sHn[w][lane+64]=h2; sHn[w][lane+96]=h3;
    g_hroot[(size_t)b*DXX+lane]=h0; g_hroot[(size_t)b*DXX+lane+32]=h1;
    g_hroot[(size_t)b*DXX+lane+64]=h2; g_hroot[(size_t)b*DXX+lane+96]=h3;
    float qq = wredsum(h0*h0+h1*h1+h2*h2+h3*h3);
    if (lane==0) g_hrootsq[b]=qq;
  }
  float muv[NNB], rsv[NNB];
  #pragma unroll
  for (int r=1; r<MM; r++){
    const float* Hr = HR + r*GN;
    float a0=Hr[lane], a1=Hr[lane+32], a2=Hr[lane+64], a3=Hr[lane+96];
    float s = wredsum(a0+a1+a2+a3);
    float mu = s*(1.f/FIN);
    float d0=a0-mu,d1=a1-mu,d2=a2-mu,d3=a3-mu;
    float s2 = wredsum(d0*d0+d1*d1+d2*d2+d3*d3);
    muv[r-1]=mu; rsv[r-1]=rsqrtf(s2*(1.f/FIN)+1e-5f);
  }
  __syncwarp();

  if (lane < NNB){
    float c[NNB];
    #pragma unroll
    for (int i=0;i<NNB;i++) c[i]=sDm[w][1+i][1+lane];
    net_sort9(c);
    #pragma unroll
    for (int i=0;i<NNB;i++) sHS[w][i][lane]=c[i];
  }
  __syncwarp();
  if (lane < NNB){
    float mu=0.f;
    #pragma unroll
    for (int j=0;j<NNB;j++) mu+=sHS[w][lane][j];
    mu *= (1.f/NNB);
    float var=0.f;
    #pragma unroll
    for (int j=0;j<NNB;j++){ float d=sHS[w][lane][j]-mu; var+=d*d; }
    var *= (1.f/NNB);
    float rstd=rsqrtf(var+1e-5f);
    #pragma unroll
    for (int j=0;j<NNB;j++) sHS[w][lane][j]=(sHS[w][lane][j]-mu)*rstd*sg[j]+sb[j];
  }
  __syncwarp();

  // ---- feat projections + network argsort + A-store ----
  {
    float cSgl=g_cSg[lane], cCbl=g_cCb[lane];
    float pv[NNB]; int pi[NNB];
    #pragma unroll
    for (int m=0;m<NNB;m++){
      pv[m] = rsv[m]*(HR[(1+m)*GN+128+lane] - muv[m]*cSgl) + cCbl;
      pi[m] = m;
    }
    net_argsort9(pv, pi);
    float t1=0.f;
    #pragma unroll
    for (int j=0;j<NNB;j++){
      float wv = sVm[w][pi[j]]*vsi;
      float p = pv[j];
      g_Afeat[(size_t)b*576 + j*LL + lane]       = -2.f*wv*p;
      g_Afeat[(size_t)b*576 + 288 + j*LL + lane] = wv;
      t1 += wv*p*p;
    }
    t1 = wredsum(t1);
    if (lane==0) g_T1feat[b]=t1;
  }
  // ---- str projections + network argsort + A-store ----
  {
    float pv[NNB]; int pi[NNB];
    #pragma unroll
    for (int m=0;m<NNB;m++){
      float v2=0.f;
      #pragma unroll
      for (int j=0;j<NNB;j++) v2 += sHS[w][m][j]*sTnsT[j][lane];
      pv[m]=v2; pi[m]=m;
    }
    net_argsort9(pv, pi);
    float t1=0.f;
    #pragma unroll
    for (int j=0;j<NNB;j++){
      float wv = sVm[w][pi[j]]*vsi;
      float p = pv[j];
      g_Astr[(size_t)b*576 + j*LL + lane]       = -2.f*wv*p;
      g_Astr[(size_t)b*576 + 288 + j*LL + lane] = wv;
      t1 += wv*p*p;
    }
    t1 = wredsum(t1);
    if (lane==0) g_T1str[b]=t1;
  }
  if (lane==0){
    float pv[NNB]; int pi[NNB];
    #pragma unroll
    for (int j=0;j<NNB;j++){ pv[j]=sDm[w][0][1+j]; pi[j]=j; }
    net_argsort9(pv, pi);
    float S=0.f;
    #pragma unroll
    for (int j=0;j<NNB;j++){
      float wv=sVm[w][pi[j]]*vsi;
      float v=pv[j];
      g_Arad[(size_t)b*18+j]   = -2.f*wv*v;
      g_Arad[(size_t)b*18+9+j] = wv;
      S += wv*v*v;
    }
    g_Srad[b]=S;
  }
  {
    float v = wn_b1[lane];
    #pragma unroll 8
    for (int d=0; d<DXX; d++) v += sHn[w][d]*wn_w1[d*32+lane];
    g_hb[(size_t)b*32+lane]=v;
  }
  {
    float cSga=g_cSg[32+lane], cCba=g_cCb[32+lane];
    float s=0.f;
    #pragma unroll
    for (int m=0;m<NNB;m++){
      float av = rsv[m]*(HR[(1+m)*GN+160+lane] - muv[m]*cSga) + cCba;
      s += sVm[w][m]*av;
    }
    float hid = fmaxf(an_b1[lane] + s*vsi, 0.f);
    float vv = wredsum(hid*an_w2[lane]);
    if (lane==0)
      g_alpha[b] = 1.0f/(1.0f+expf(-(alpha_raw[0] + vv + an_b2[0])));
  }
}

// ------------------- kernel 3: register-tiled combine -------------------
__device__ __forceinline__ void p2_loadA(const float* Aptr, int b0, int c0,
                                         int strideA, float scale,
                                         float (*sA)[20], int tid){
  #pragma unroll
  for (int it=0; it<2; it++){
    int u = tid + it*128;
    int bb = u >> 4, cq = u & 15;
    float4 v = *(const float4*)&Aptr[(size_t)(b0+bb)*strideA + c0 + cq*4];
    int c = cq*4;
    sA[c+0][bb]=v.x*scale; sA[c+1][bb]=v.y*scale;
    sA[c+2][bb]=v.z*scale; sA[c+3][bb]=v.w*scale;
  }
}
__device__ __forceinline__ void p2_loadP(const float* Pptr, int c0,
                                         int strideP, float (*sP)[68], int tid){
  #pragma unroll
  for (int it=0; it<8; it++){
    int u = tid + it*128;
    int kk = u >> 4, cq = u & 15;
    float4 v = *(const float4*)&Pptr[(size_t)kk*strideP + c0 + cq*4];
    int c = cq*4;
    sP[c+0][kk]=v.x; sP[c+1][kk]=v.y; sP[c+2][kk]=v.z; sP[c+3][kk]=v.w;
  }
}
__device__ __forceinline__ void p2_compute(const float (*sA)[20], const float (*sP)[68],
                                           int bg, int kg, float* acc){
  #pragma unroll 8
  for (int c=0;c<64;c++){
    float2 a = *(const float2*)&sA[c][bg*2];
    float4 p = *(const float4*)&sP[c][kg*4];
    acc[0]+=a.x*p.x; acc[1]+=a.x*p.y; acc[2]+=a.x*p.z; acc[3]+=a.x*p.w;
    acc[4]+=a.y*p.x; acc[5]+=a.y*p.y; acc[6]+=a.y*p.z; acc[7]+=a.y*p.w;
  }
}

__global__ __launch_bounds__(128)
void k_phase2(const float* wn_w2, const float* wn_b2, const float* w_raw,
              const float* log_gamma, float* out)
{
  int tid = threadIdx.x;
  int bg = tid >> 4;
  int kg = tid & 15;
  int b0 = blockIdx.x * TB2;

  __shared__ __align__(16) float sA[64][20];
  __shared__ __align__(16) float sP[64][68];
  __shared__ float sHb[TB2][33];
  __shared__ float sHp[KK][33];
  __shared__ float sArad[TB2][19];
  __shared__ float sPrad[KK][19];
  __shared__ float sScB[TB2][5];
  __shared__ float sHpsq[KK];
  __shared__ float sW2[32];

  for (int idx=tid; idx<TB2*32; idx+=128){ int bb=idx>>5, j=idx&31; sHb[bb][j]=g_hb[(size_t)(b0+bb)*32+j]; }
  for (int idx=tid; idx<KK*32; idx+=128){ int kk=idx>>5, j=idx&31; sHp[kk][j]=g_hp[kk*32+j]; }
  for (int idx=tid; idx<TB2*18; idx+=128){ int bb=idx/18, j=idx%18; sArad[bb][j]=g_Arad[(size_t)(b0+bb)*18+j]; }
  for (int idx=tid; idx<KK*18; idx+=128){ int kk=idx/18, j=idx%18; sPrad[kk][j]=g_Prad[kk*18+j]; }
  for (int idx=tid; idx<TB2*5; idx+=128){
    int bb=idx/5, q=idx%5, bgl=b0+bb;
    float v;
    switch(q){
      case 0: v=g_T1feat[bgl]; break;
      case 1: v=g_T1str[bgl];  break;
      case 2: v=g_Srad[bgl];   break;
      case 3: v=g_hrootsq[bgl];break;
      default:v=g_alpha[bgl];
    }
    sScB[bb][q]=v;
  }
  if (tid < KK) sHpsq[tid]=g_hproto_sq[tid];
  if (tid < 32) sW2[tid]=wn_w2[tid];

  float accF[8], accS[8], accR[8];
  #pragma unroll
  for (int q=0;q<8;q++){ accF[q]=0.f; accS[q]=0.f; accR[q]=0.f; }

  for (int ch=0; ch<9; ch++){
    __syncthreads();
    p2_loadA(g_Afeat, b0, ch*64, 576, 1.f, sA, tid);
    p2_loadP(g_Pfeat, ch*64, 576, sP, tid);
    __syncthreads();
    p2_compute(sA, sP, bg, kg, accF);
  }
  for (int ch=0; ch<9; ch++){
    __syncthreads();
    p2_loadA(g_Astr, b0, ch*64, 576, 1.f, sA, tid);
    p2_loadP(g_Pstr, ch*64, 576, sP, tid);
    __syncthreads();
    p2_compute(sA, sP, bg, kg, accS);
  }
  for (int ch=0; ch<2; ch++){
    __syncthreads();
    p2_loadA(g_hroot, b0, ch*64, DXX, -2.f, sA, tid);
    p2_loadP(g_hproto_root, ch*64, DXX, sP, tid);
    __syncthreads();
    p2_compute(sA, sP, bg, kg, accR);
  }

  float accD[8];
  #pragma unroll
  for (int q=0;q<8;q++) accD[q]=0.f;
  #pragma unroll
  for (int j=0;j<18;j++){
    float a0=sArad[bg*2+0][j], a1=sArad[bg*2+1][j];
    float p0=sPrad[kg*4+0][j], p1=sPrad[kg*4+1][j], p2=sPrad[kg*4+2][j], p3=sPrad[kg*4+3][j];
    accD[0]+=a0*p0; accD[1]+=a0*p1; accD[2]+=a0*p2; accD[3]+=a0*p3;
    accD[4]+=a1*p0; accD[5]+=a1*p1; accD[6]+=a1*p2; accD[7]+=a1*p3;
  }

  float wlog[8];
  #pragma unroll
  for (int q=0;q<8;q++) wlog[q]=0.f;
  #pragma unroll 8
  for (int j=0;j<32;j++){
    float w2 = sW2[j];
    float b0v=sHb[bg*2+0][j], b1v=sHb[bg*2+1][j];
    float p0=sHp[kg*4+0][j], p1=sHp[kg*4+1][j], p2=sHp[kg*4+2][j], p3=sHp[kg*4+3][j];
    wlog[0]+=fmaxf(b0v+p0,0.f)*w2; wlog[1]+=fmaxf(b0v+p1,0.f)*w2;
    wlog[2]+=fmaxf(b0v+p2,0.f)*w2; wlog[3]+=fmaxf(b0v+p3,0.f)*w2;
    wlog[4]+=fmaxf(b1v+p0,0.f)*w2; wlog[5]+=fmaxf(b1v+p1,0.f)*w2;
    wlog[6]+=fmaxf(b1v+p2,0.f)*w2; wlog[7]+=fmaxf(b1v+p3,0.f)*w2;
  }

  float wraw = w_raw[0], wb2 = wn_b2[0];
  float gamma = expf(log_gamma[0]);

  #pragma unroll
  for (int i=0;i<2;i++){
    int bi = bg*2+i;
    float T1f=sScB[bi][0], T1s=sScB[bi][1], Sr=sScB[bi][2], hrsq=sScB[bi][3], al=sScB[bi][4];
    float res[4];
    #pragma unroll
    for (int j=0;j<4;j++){
      int q = i*4+j;
      int kk = kg*4+j;
      float wgt = 1.f/(1.f+expf(-(wraw + wlog[q] + wb2)));
      float drf = hrsq + sHpsq[kk] + accR[q];
      float swf = (T1f + accF[q])*(1.f/(float)LL);
      float sws = (T1s + accS[q])*(1.f/(float)LL);
      float rad = Sr + accD[q];
      float df = wgt*drf + (1.f-wgt)*swf;
      float ds = wgt*rad + (1.f-wgt)*sws;
      float dfgw = al*df + (1.f-al)*ds;
      res[j] = expf(-gamma*dfgw);
    }
    *(float4*)&out[(size_t)(b0+bi)*KK + kg*4] = make_float4(res[0],res[1],res[2],res[3]);
  }
}

// ------------------- launcher -------------------
extern "C" void kernel_launch(void* const* d_in, const int* in_sizes, int n_in,
                              void* d_out, int out_size)
{
  const float* adj        = (const float*)d_in[0];
  const float* features   = (const float*)d_in[1];
  const int*   idxs       = (const int*)  d_in[2];
  const float* x_lin_w    = (const float*)d_in[3];
  const float* x_lin_b    = (const float*)d_in[4];
  const float* x_ln_g     = (const float*)d_in[5];
  const float* x_ln_b     = (const float*)d_in[6];
  const float* s_ln_g     = (const float*)d_in[7];
  const float* s_ln_b     = (const float*)d_in[8];
  const float* theta_x    = (const float*)d_in[9];
  const float* theta_s    = (const float*)d_in[10];
  const float* alpha_raw  = (const float*)d_in[11];
  const float* an_w1      = (const float*)d_in[12];
  const float* an_b1      = (const float*)d_in[13];
  const float* an_w2      = (const float*)d_in[14];
  const float* an_b2      = (const float*)d_in[15];
  const float* wn_w1      = (const float*)d_in[16];
  const float* wn_b1      = (const float*)d_in[17];
  const float* wn_w2      = (const float*)d_in[18];
  const float* wn_b2      = (const float*)d_in[19];
  const float* w_raw      = (const float*)d_in[20];
  const float* proto_root = (const float*)d_in[21];
  const float* proto_neigh= (const float*)d_in[22];
  const float* proto_rad  = (const float*)d_in[23];
  const float* proto_dn   = (const float*)d_in[24];
  const float* log_gamma  = (const float*)d_in[25];
  float* out = (float*)d_out;

  cudaFuncSetAttribute(k_lin_mma, cudaFuncAttributeMaxDynamicSharedMemorySize, SMEM_LIN);

  k_tn<<<1,128>>>(theta_x, theta_s);
  k_prep<<<41,256>>>(x_lin_w, x_lin_b, x_ln_g, x_ln_b, an_w1);
  k_prepB<<<192,256>>>();
  k_lin_mma<<<(BB*MM)/128 + 5, 256, SMEM_LIN>>>(features, idxs, proto_root, proto_neigh);
  k_proto_lite<<<KK/8,256>>>(x_ln_g, x_ln_b, s_ln_g, s_ln_b,
                             wn_w1, proto_rad, proto_dn);
  k_phase1b<<<BB/8,256>>>(adj, idxs, x_ln_g, x_ln_b, s_ln_g, s_ln_b,
                          an_b1, an_w2, an_b2, wn_w1, wn_b1, alpha_raw);
  k_phase2<<<BB/TB2,128>>>(wn_w2, wn_b2, w_raw, log_gamma, out);
}

// round 9
// speedup vs baseline: 1.4538x; 1.4538x over previous
#include <cuda_runtime.h>
#include <cuda_bf16.h>
#include <math.h>
#include <stdint.h>

#define BB   8192
#define MM   10
#define NNB  9
#define FIN  128
#define DXX  128
#define KK   64
#define LL   32
#define NALL 100000
#define GN   192
#define TB2  16

// ------------------- device scratch -------------------
__device__ float g_tnxT[FIN*LL];
__device__ float g_tnsT[NNB*LL];
__device__ float g_Bmat[FIN*GN];
__device__ float g_biasv[GN];
__device__ float g_cSg[64];
__device__ float g_cCb[64];
__device__ float g_Hraw[(size_t)BB*MM*GN];
__device__ __align__(16) __nv_bfloat16 g_BtileH[2*GN*136];   // [half][n][k_pad136]

__device__ float g_hproto_root[KK*DXX];
__device__ float g_hproto_sq[KK];
__device__ float g_hp[KK*32];
__device__ float g_Pfeat[KK*576];
__device__ float g_Pstr[KK*576];
__device__ float g_Prad[KK*18];

__device__ float g_hroot[BB*DXX];
__device__ float g_hrootsq[BB];
__device__ float g_hb[BB*32];
__device__ float g_alpha[BB];
__device__ float g_Afeat[(size_t)BB*576];
__device__ float g_T1feat[BB];
__device__ float g_Astr[(size_t)BB*576];
__device__ float g_T1str[BB];
__device__ float g_Arad[BB*18];
__device__ float g_Srad[BB];

// ------------------- helpers (insertion sorts — empirically faster than networks) ----
__device__ __forceinline__ void sort9(float* v){
  for (int a=1;a<NNB;a++){
    float x=v[a]; int c=a-1;
    while (c>=0 && v[c]>x){ v[c+1]=v[c]; c--; }
    v[c+1]=x;
  }
}
__device__ __forceinline__ void argsort9(const float* v, int* ord){
  for (int a=0;a<NNB;a++) ord[a]=a;
  for (int a=1;a<NNB;a++){
    int o=ord[a]; float x=v[o]; int c=a-1;
    while (c>=0 && v[ord[c]]>x){ ord[c+1]=ord[c]; c--; }
    ord[c+1]=o;
  }
}
__device__ __forceinline__ float wredsum(float v){
  #pragma unroll
  for (int o=16;o;o>>=1) v += __shfl_xor_sync(0xffffffffu, v, o);
  return v;
}
__device__ __forceinline__ void ln_rows(float (*sH)[FIN], int nrows,
                                        const float* g, const float* b, int t){
  int w = t>>5, lane = t&31;
  for (int r=w; r<nrows; r+=4){
    float s=0.f;
    for (int j=lane;j<FIN;j+=32) s += sH[r][j];
    s = wredsum(s);
    float mu = s*(1.f/FIN);
    float s2=0.f;
    for (int j=lane;j<FIN;j+=32){ float d=sH[r][j]-mu; s2 += d*d; }
    s2 = wredsum(s2);
    float rstd = rsqrtf(s2*(1.f/FIN)+1e-5f);
    for (int j=lane;j<FIN;j+=32) sH[r][j] = (sH[r][j]-mu)*rstd*g[j] + b[j];
  }
}
__device__ __forceinline__ uint32_t smem_u32(const void* p){
  uint32_t a;
  asm("{ .reg .u64 t; cvta.to.shared.u64 t, %1; cvt.u32.u64 %0, t; }" : "=r"(a) : "l"(p));
  return a;
}
// ---- sm_80-compatible tensor core ops ----
__device__ __forceinline__ void ldsm_x4(uint32_t* r, uint32_t addr){
  asm volatile("ldmatrix.sync.aligned.m8n8.x4.shared.b16 {%0,%1,%2,%3}, [%4];"
    : "=r"(r[0]),"=r"(r[1]),"=r"(r[2]),"=r"(r[3]) : "r"(addr));
}
__device__ __forceinline__ void ldsm_x2(uint32_t* r, uint32_t addr){
  asm volatile("ldmatrix.sync.aligned.m8n8.x2.shared.b16 {%0,%1}, [%2];"
    : "=r"(r[0]),"=r"(r[1]) : "r"(addr));
}
__device__ __forceinline__ void mma16816(float* c, const uint32_t* a, const uint32_t* b){
  asm volatile(
    "mma.sync.aligned.m16n8k16.row.col.f32.bf16.bf16.f32 "
    "{%0,%1,%2,%3}, {%4,%5,%6,%7}, {%8,%9}, {%0,%1,%2,%3};"
    : "+f"(c[0]),"+f"(c[1]),"+f"(c[2]),"+f"(c[3])
    : "r"(a[0]),"r"(a[1]),"r"(a[2]),"r"(a[3]), "r"(b[0]),"r"(b[1]));
}

// ------------------- kernel 0: normalize thetas -------------------
__global__ void k_tn(const float* theta_x, const float* theta_s){
  int t = threadIdx.x, w=t>>5, lane=t&31;
  for (int row=w; row<LL; row+=4){
    float s=0.f;
    for (int j=lane;j<FIN;j+=32){ float v=theta_x[row*FIN+j]; s+=v*v; }
    s = wredsum(s);
    float inv = 1.0f/sqrtf(s);
    for (int j=lane;j<FIN;j+=32) g_tnxT[j*LL+row] = theta_x[row*FIN+j]*inv;
  }
  if (t < LL){
    float s=0.f;
    for (int j=0;j<NNB;j++){ float v=theta_s[t*NNB+j]; s+=v*v; }
    float inv = 1.0f/sqrtf(s);
    for (int j=0;j<NNB;j++) g_tnsT[j*LL+t] = theta_s[t*NNB+j]*inv;
  }
}

// ------------------- kernel 0b: build folded B matrix -------------------
__global__ void k_prep(const float* Wlin, const float* blin,
                       const float* lng, const float* lnb,
                       const float* an_w1){
  int bid = blockIdx.x, t = threadIdx.x;
  if (bid < 32){
    int out = bid*256 + t;
    int i = out >> 6, c = out & 63;
    float acc = 0.f;
    for (int d=0; d<FIN; d++){
      float th = (c<32) ? g_tnxT[d*LL + c] : an_w1[d*32 + (c-32)];
      acc += Wlin[i*DXX + d] * (lng[d]*th);
    }
    g_Bmat[i*GN + 128 + c] = acc;
  } else if (bid < 40){
    int base = (bid-32)*2048;
    for (int it=0; it<8; it++){
      int u = base + t + it*256;
      g_Bmat[(u>>7)*GN + (u&127)] = Wlin[u];
    }
  } else {
    if (t < 128) g_biasv[t] = blin[t];
    if (t < 64){
      float bs=0.f, sg=0.f, cb=0.f;
      for (int d=0; d<FIN; d++){
        float th = (t<32) ? g_tnxT[d*LL + t] : an_w1[d*32 + (t-32)];
        float v = lng[d]*th;
        bs += blin[d]*v;
        sg += v;
        cb += lnb[d]*th;
      }
      g_biasv[128+t]=bs; g_cSg[t]=sg; g_cCb[t]=cb;
    }
  }
}

// ------------------- kernel 0c: bf16 hi/lo padded B tiles [half][n][136] -------------------
__global__ void k_prepB(){
  int e = blockIdx.x*256 + threadIdx.x;     // < 49152 = 2*192*128
  int half = e / 24576;
  int r = e % 24576;
  int n = r >> 7, k = r & 127;
  float v = g_Bmat[k*GN + n];
  __nv_bfloat16 hb = __float2bfloat16(v);
  __nv_bfloat16 val = (half==0) ? hb : __float2bfloat16(v - __bfloat162float(hb));
  g_BtileH[(half*GN + n)*136 + k] = val;
}

// ------------------- kernel 1: per-prototype precompute (grid=KK, block=128) -------------------
__global__ void k_proto(const float* Wlin, const float* blin,
                        const float* lng, const float* lnb,
                        const float* sg, const float* sb,
                        const float* wn_w1,
                        const float* proto_root, const float* proto_neigh,
                        const float* proto_rad, const float* proto_dn)
{
  int k = blockIdx.x, t = threadIdx.x;
  __shared__ __align__(16) float sXT[FIN][12];
  __shared__ float sH[MM][FIN];
  __shared__ float sPp[NNB][LL];
  __shared__ float sC[NNB][NNB];
  __shared__ float sCS[NNB][NNB];
  __shared__ float sRed[4];

  sXT[t][0] = proto_root[k*FIN + t];
  for (int m=0;m<NNB;m++) sXT[t][m+1] = proto_neigh[(k*NNB+m)*FIN + t];
  __syncthreads();

  float acc[MM];
  {
    float bias = blin[t];
    #pragma unroll
    for (int r=0;r<MM;r++) acc[r]=bias;
    for (int i=0;i<FIN;i++){
      float wv = Wlin[i*DXX+t];
      float4 xa = *(const float4*)&sXT[i][0];
      float4 xb = *(const float4*)&sXT[i][4];
      float2 xc = *(const float2*)&sXT[i][8];
      acc[0]+=xa.x*wv; acc[1]+=xa.y*wv; acc[2]+=xa.z*wv; acc[3]+=xa.w*wv;
      acc[4]+=xb.x*wv; acc[5]+=xb.y*wv; acc[6]+=xb.z*wv; acc[7]+=xb.w*wv;
      acc[8]+=xc.x*wv; acc[9]+=xc.y*wv;
    }
  }
  #pragma unroll
  for (int r=0;r<MM;r++) sH[r][t]=acc[r];
  __syncthreads();
  ln_rows(sH, MM, lng, lnb, t);
  __syncthreads();

  g_hproto_root[k*DXX+t] = sH[0][t];
  {
    float v = sH[0][t]; v*=v;
    v = wredsum(v);
    if ((t&31)==0) sRed[t>>5]=v;
  }
  __syncthreads();
  if (t==0) g_hproto_sq[k] = sRed[0]+sRed[1]+sRed[2]+sRed[3];
  if (t<32){
    float v=0.f;
    for (int d=0;d<DXX;d++) v += sH[0][d]*wn_w1[(DXX+d)*32 + t];
    g_hp[k*32+t]=v;
  }
  for (int q=t;q<NNB*LL;q+=blockDim.x){
    int m=q/LL, l=q%LL;
    float v=0.f;
    for (int d=0;d<DXX;d++) v += sH[1+m][d]*g_tnxT[d*LL+l];
    sPp[m][l]=v;
  }
  __syncthreads();
  if (t<LL){
    float vals[NNB];
    for (int m=0;m<NNB;m++) vals[m]=sPp[m][t];
    sort9(vals);
    for (int j=0;j<NNB;j++){
      float v=vals[j];
      g_Pfeat[k*576 + j*LL + t]       = v;
      g_Pfeat[k*576 + 288 + j*LL + t] = v*v;
    }
  }
  if (t < 36){
    int p=t, i=0;
    while (p >= NNB-1-i){ p -= NNB-1-i; i++; }
    int j = i+1+p;
    float x = proto_dn[t*KK + k];
    float s = 1.0f/(1.0f+expf(-x));
    sC[i][j]=s; sC[j][i]=s;
  }
  if (t < NNB) sC[t][t]=0.f;
  __syncthreads();
  if (t < NNB){
    float c[NNB];
    for (int i=0;i<NNB;i++) c[i]=sC[i][t];
    sort9(c);
    for (int i=0;i<NNB;i++) sCS[i][t]=c[i];
  }
  __syncthreads();
  if (t < NNB){
    float mu=0.f; for(int j=0;j<NNB;j++) mu+=sCS[t][j]; mu*=(1.f/NNB);
    float var=0.f; for(int j=0;j<NNB;j++){float d=sCS[t][j]-mu; var+=d*d;} var*=(1.f/NNB);
    float rstd = rsqrtf(var+1e-5f);
    for (int j=0;j<NNB;j++) sCS[t][j] = (sCS[t][j]-mu)*rstd*sg[j]+sb[j];
  }
  __syncthreads();
  if (t<LL){
    float vals[NNB];
    for (int m=0;m<NNB;m++){
      float v=0.f;
      for (int j=0;j<NNB;j++) v += sCS[m][j]*g_tnsT[j*LL+t];
      vals[m]=v;
    }
    sort9(vals);
    for (int j=0;j<NNB;j++){
      float v=vals[j];
      g_Pstr[k*576 + j*LL + t]       = v;
      g_Pstr[k*576 + 288 + j*LL + t] = v*v;
    }
  }
  if (t==0){
    float r[NNB];
    for (int j=0;j<NNB;j++) r[j]=proto_rad[k*NNB+j];
    sort9(r);
    for (int j=0;j<NNB;j++){ g_Prad[k*18+j]=r[j]; g_Prad[k*18+9+j]=r[j]*r[j]; }
  }
}

// ------------------- kernel 2a: split-bf16 mma.sync gathered GEMM (512 thr, 16 warps) ----
// Hraw[81920][192] = gather(features) @ Bmat + biasv ;  Ahi*Bhi + Alo*Bhi + Ahi*Blo
#define SM_IDX   0
#define SM_BIAS  512
#define SM_AHI   2048
#define SM_ALO   (SM_AHI + 128*136*2)
#define SM_BHI   (SM_ALO + 128*136*2)
#define SM_BLO   (SM_BHI + 192*136*2)
#define SMEM_LIN (SM_BLO + 192*136*2)      // 176128 bytes
#define STG_STRIDE 196

__global__ __launch_bounds__(512)
void k_lin_mma(const float* features, const int* idxs)
{
  extern __shared__ char smem[];
  int tid = threadIdx.x;
  int wid = tid >> 5, lane = tid & 31;
  size_t row0 = (size_t)blockIdx.x * 128;
  int* sIdx = (int*)(smem + SM_IDX);
  float* sBias = (float*)(smem + SM_BIAS);

  if (tid < 128) sIdx[tid] = idxs[row0 + tid];
  if (tid >= 256 && tid < 448) sBias[tid-256] = g_biasv[tid-256];

  // B copy: 104448 B = 6528 uint4
  {
    const uint4* src = (const uint4*)g_BtileH;
    uint4* dst = (uint4*)(smem + SM_BHI);
    #pragma unroll
    for (int i=0;i<13;i++){
      int u = tid + i*512;
      if (u < 6528) dst[u] = src[u];
    }
  }
  __syncthreads();

  // A gather + hi/lo split into padded [128][136] bf16 tiles
  #pragma unroll
  for (int i=0;i<8;i++){
    int u = tid + i*512;             // 0..4095 = 128 rows x 32 float4
    int row = u >> 5, q = u & 31;
    int id = sIdx[row];
    float4 v;
    if (id == NALL) v = make_float4(0.f,0.f,0.f,0.f);
    else v = *(const float4*)&features[(size_t)id*FIN + q*4];
    __nv_bfloat162 h01 = __floats2bfloat162_rn(v.x, v.y);
    __nv_bfloat162 h23 = __floats2bfloat162_rn(v.z, v.w);
    float2 f01 = __bfloat1622float2(h01);
    float2 f23 = __bfloat1622float2(h23);
    __nv_bfloat162 l01 = __floats2bfloat162_rn(v.x - f01.x, v.y - f01.y);
    __nv_bfloat162 l23 = __floats2bfloat162_rn(v.z - f23.x, v.w - f23.y);
    uint32_t off = (uint32_t)(row*136 + q*4)*2;
    *(__nv_bfloat162*)(smem + SM_AHI + off)     = h01;
    *(__nv_bfloat162*)(smem + SM_AHI + off + 4) = h23;
    *(__nv_bfloat162*)(smem + SM_ALO + off)     = l01;
    *(__nv_bfloat162*)(smem + SM_ALO + off + 4) = l23;
  }
  __syncthreads();

  // 16 warps: 8(m) x 2(n); each warp owns a 16(m) x 96(n) tile
  int wm = wid >> 1, wn = wid & 1;
  int mbase = wm*16, nbase = wn*96;
  uint32_t sb = smem_u32(smem);

  float acc[12][4];
  #pragma unroll
  for (int j=0;j<12;j++)
    #pragma unroll
    for (int q=0;q<4;q++) acc[j][q]=0.f;

  int aRow = mbase + ((lane>>3)&1)*8 + (lane&7);
  int aK   = (lane>>4)*8;
  int bRow = nbase + (lane&7);
  int bK   = ((lane>>3)&1)*8;

  // pass A: Bhi x (Ahi, Alo)
  #pragma unroll
  for (int kc=0; kc<8; kc++){
    uint32_t bf[12][2];
    #pragma unroll
    for (int j=0;j<12;j++)
      ldsm_x2(bf[j], sb + SM_BHI + (uint32_t)((bRow + j*8)*136 + kc*16 + bK)*2);
    uint32_t af[4];
    ldsm_x4(af, sb + SM_AHI + (uint32_t)(aRow*136 + kc*16 + aK)*2);
    #pragma unroll
    for (int j=0;j<12;j++) mma16816(acc[j], af, bf[j]);
    ldsm_x4(af, sb + SM_ALO + (uint32_t)(aRow*136 + kc*16 + aK)*2);
    #pragma unroll
    for (int j=0;j<12;j++) mma16816(acc[j], af, bf[j]);
  }
  // pass B: Blo x Ahi
  #pragma unroll
  for (int kc=0; kc<8; kc++){
    uint32_t bf[12][2];
    #pragma unroll
    for (int j=0;j<12;j++)
      ldsm_x2(bf[j], sb + SM_BLO + (uint32_t)((bRow + j*8)*136 + kc*16 + bK)*2);
    uint32_t af[4];
    ldsm_x4(af, sb + SM_AHI + (uint32_t)(aRow*136 + kc*16 + aK)*2);
    #pragma unroll
    for (int j=0;j<12;j++) mma16816(acc[j], af, bf[j]);
  }
  __syncthreads();   // A/B regions dead; reuse as stage

  // epilogue: acc (+bias) -> stage smem -> coalesced STG
  float* stage = (float*)(smem + SM_AHI);
  {
    int r = lane >> 2, c2 = 2*(lane & 3);
    int rr = mbase + r;
    #pragma unroll
    for (int j=0;j<12;j++){
      int cc = nbase + j*8 + c2;
      float b0 = sBias[cc], b1 = sBias[cc+1];
      *(float2*)&stage[rr*STG_STRIDE + cc]     = make_float2(acc[j][0]+b0, acc[j][1]+b1);
      *(float2*)&stage[(rr+8)*STG_STRIDE + cc] = make_float2(acc[j][2]+b0, acc[j][3]+b1);
    }
  }
  __syncthreads();
  #pragma unroll
  for (int i=0;i<12;i++){
    int u = tid + i*512;                 // 0..6143 = 128 rows x 48 float4
    int row = u/48, q = u%48;
    *(float4*)&g_Hraw[(row0 + row)*GN + q*4] = *(float4*)&stage[row*STG_STRIDE + q*4];
  }
}

// ------------------- kernel 2b: warp-per-b light pass (grid=BB/8, block=256) -------------------
__global__ __launch_bounds__(256)
void k_phase1b(const float* adj, const int* idxs,
               const float* lng, const float* lnb,
               const float* sg, const float* sb,
               const float* an_b1, const float* an_w2, const float* an_b2,
               const float* wn_w1, const float* wn_b1,
               const float* alpha_raw)
{
  int tid = threadIdx.x;
  int w = tid >> 5, lane = tid & 31;
  int b = blockIdx.x*8 + w;

  __shared__ float sDm[8][MM][MM];
  __shared__ float sHS[8][NNB][NNB];
  __shared__ float sHn[8][FIN];
  __shared__ float sVm[8][NNB];
  __shared__ unsigned sNbr[8][MM];
  __shared__ float sTnsT[NNB][32];

  for (int u=tid; u<NNB*32; u+=256) sTnsT[u>>5][u&31] = g_tnsT[u];

  const float* HR = g_Hraw + (size_t)b*MM*GN;

  if (lane < MM){
    int idv = idxs[b*MM + lane];
    if (lane >= 1) sVm[w][lane-1] = (idv != NALL) ? 1.f : 0.f;
    unsigned nb=0;
    const float* arow = adj + (size_t)b*MM*MM + lane*MM;
    #pragma unroll
    for (int j=0;j<MM;j++) if (arow[j] > 1e-5f) nb |= (1u<<j);
    sNbr[w][lane]=nb;
  }
  __syncthreads();

  float vs = 0.f;
  #pragma unroll
  for (int j=0;j<NNB;j++) vs += sVm[w][j];
  float vsi = 1.f/(vs + 1e-9f);

  if (lane < MM){
    float drow[MM];
    #pragma unroll
    for (int j=0;j<MM;j++) drow[j] = (j==lane)?0.f:10.f;
    unsigned reach = 1u<<lane, frontier = 1u<<lane;
    for (int step=1; step<MM; step++){
      unsigned nxt=0;
      #pragma unroll
      for (int v=0;v<MM;v++) if (frontier & (1u<<v)) nxt |= sNbr[w][v];
      nxt &= ~reach;
      if (!nxt) break;
      #pragma unroll
      for (int v=0;v<MM;v++) if (nxt & (1u<<v)) drow[v]=(float)step;
      reach |= nxt; frontier = nxt;
    }
    #pragma unroll
    for (int j=0;j<MM;j++) sDm[w][lane][j]=drow[j];
  }
  __syncwarp();
  for (int q=lane; q<MM*MM; q+=32){
    int i=q/MM, j=q%MM;
    float fi = (i==0)?1.f:sVm[w][i-1];
    float fj = (j==0)?1.f:sVm[w][j-1];
    sDm[w][i][j] = (fi*fj>0.f) ? sDm[w][i][j]*0.1f : 1.0f;
  }
  __syncwarp();

  float lg0=lng[lane], lg1=lng[lane+32], lg2=lng[lane+64], lg3=lng[lane+96];
  float lb0=lnb[lane], lb1=lnb[lane+32], lb2=lnb[lane+64], lb3=lnb[lane+96];
  {
    float a0=HR[lane], a1=HR[lane+32], a2=HR[lane+64], a3=HR[lane+96];
    float s = wredsum(a0+a1+a2+a3);
    float mu = s*(1.f/FIN);
    float d0=a0-mu,d1=a1-mu,d2=a2-mu,d3=a3-mu;
    float s2 = wredsum(d0*d0+d1*d1+d2*d2+d3*d3);
    float rs = rsqrtf(s2*(1.f/FIN)+1e-5f);
    float h0=d0*rs*lg0+lb0, h1=d1*rs*lg1+lb1, h2=d2*rs*lg2+lb2, h3=d3*rs*lg3+lb3;
    sHn[w][lane]=h0; sHn[w][lane+32]=h1; sHn[w][lane+64]=h2; sHn[w][lane+96]=h3;
    g_hroot[(size_t)b*DXX+lane]=h0; g_hroot[(size_t)b*DXX+lane+32]=h1;
    g_hroot[(size_t)b*DXX+lane+64]=h2; g_hroot[(size_t)b*DXX+lane+96]=h3;
    float qq = wredsum(h0*h0+h1*h1+h2*h2+h3*h3);
    if (lane==0) g_hrootsq[b]=qq;
  }
  float muv[NNB], rsv[NNB];
  #pragma unroll
  for (int r=1; r<MM; r++){
    const float* Hr = HR + r*GN;
    float a0=Hr[lane], a1=Hr[lane+32], a2=Hr[lane+64], a3=Hr[lane+96];
    float s = wredsum(a0+a1+a2+a3);
    float mu = s*(1.f/FIN);
    float d0=a0-mu,d1=a1-mu,d2=a2-mu,d3=a3-mu;
    float s2 = wredsum(d0*d0+d1*d1+d2*d2+d3*d3);
    muv[r-1]=mu; rsv[r-1]=rsqrtf(s2*(1.f/FIN)+1e-5f);
  }
  __syncwarp();

  if (lane < NNB){
    float c[NNB];
    #pragma unroll
    for (int i=0;i<NNB;i++) c[i]=sDm[w][1+i][1+lane];
    sort9(c);
    #pragma unroll
    for (int i=0;i<NNB;i++) sHS[w][i][lane]=c[i];
  }
  __syncwarp();
  if (lane < NNB){
    float mu=0.f;
    #pragma unroll
    for (int j=0;j<NNB;j++) mu+=sHS[w][lane][j];
    mu *= (1.f/NNB);
    float var=0.f;
    #pragma unroll
    for (int j=0;j<NNB;j++){ float d=sHS[w][lane][j]-mu; var+=d*d; }
    var *= (1.f/NNB);
    float rstd=rsqrtf(var+1e-5f);
    #pragma unroll
    for (int j=0;j<NNB;j++) sHS[w][lane][j]=(sHS[w][lane][j]-mu)*rstd*sg[j]+sb[j];
  }
  __syncwarp();

  {
    float cSgl=g_cSg[lane], cCbl=g_cCb[lane];
    float vals[NNB]; int ord[NNB];
    #pragma unroll
    for (int m=0;m<NNB;m++)
      vals[m] = rsv[m]*(HR[(1+m)*GN+128+lane] - muv[m]*cSgl) + cCbl;
    argsort9(vals, ord);
    float t1=0.f;
    #pragma unroll
    for (int j=0;j<NNB;j++){
      int mo=ord[j];
      float wv = sVm[w][mo]*vsi;
      float pv = vals[mo];
      g_Afeat[(size_t)b*576 + j*LL + lane]       = -2.f*wv*pv;
      g_Afeat[(size_t)b*576 + 288 + j*LL + lane] = wv;
      t1 += wv*pv*pv;
    }
    t1 = wredsum(t1);
    if (lane==0) g_T1feat[b]=t1;
  }
  {
    float vals[NNB]; int ord[NNB];
    #pragma unroll
    for (int m=0;m<NNB;m++){
      float v2=0.f;
      #pragma unroll
      for (int j=0;j<NNB;j++) v2 += sHS[w][m][j]*sTnsT[j][lane];
      vals[m]=v2;
    }
    argsort9(vals, ord);
    float t1=0.f;
    #pragma unroll
    for (int j=0;j<NNB;j++){
      int mo=ord[j];
      float wv = sVm[w][mo]*vsi;
      float pv = vals[mo];
      g_Astr[(size_t)b*576 + j*LL + lane]       = -2.f*wv*pv;
      g_Astr[(size_t)b*576 + 288 + j*LL + lane] = wv;
      t1 += wv*pv*pv;
    }
    t1 = wredsum(t1);
    if (lane==0) g_T1str[b]=t1;
  }
  if (lane==0){
    float rb[NNB]; int ord[NNB];
    #pragma unroll
    for (int j=0;j<NNB;j++) rb[j]=sDm[w][0][1+j];
    argsort9(rb, ord);
    float S=0.f;
    #pragma unroll
    for (int j=0;j<NNB;j++){
      int mo=ord[j];
      float wv=sVm[w][mo]*vsi;
      float v=rb[mo];
      g_Arad[(size_t)b*18+j]   = -2.f*wv*v;
      g_Arad[(size_t)b*18+9+j] = wv;
      S += wv*v*v;
    }
    g_Srad[b]=S;
  }
  {
    float v = wn_b1[lane];
    #pragma unroll 8
    for (int d=0; d<DXX; d++) v += sHn[w][d]*wn_w1[d*32+lane];
    g_hb[(size_t)b*32+lane]=v;
  }
  {
    float cSga=g_cSg[32+lane], cCba=g_cCb[32+lane];
    float s=0.f;
    #pragma unroll
    for (int m=0;m<NNB;m++){
      float av = rsv[m]*(HR[(1+m)*GN+160+lane] - muv[m]*cSga) + cCba;
      s += sVm[w][m]*av;
    }
    float hid = fmaxf(an_b1[lane] + s*vsi, 0.f);
    float vv = wredsum(hid*an_w2[lane]);
    if (lane==0)
      g_alpha[b] = 1.0f/(1.0f+expf(-(alpha_raw[0] + vv + an_b2[0])));
  }
}

// ------------------- kernel 3: register-tiled combine -------------------
__device__ __forceinline__ void p2_loadA(const float* Aptr, int b0, int c0,
                                         int strideA, float scale,
                                         float (*sA)[20], int tid){
  #pragma unroll
  for (int it=0; it<2; it++){
    int u = tid + it*128;
    int bb = u >> 4, cq = u & 15;
    float4 v = *(const float4*)&Aptr[(size_t)(b0+bb)*strideA + c0 + cq*4];
    int c = cq*4;
    sA[c+0][bb]=v.x*scale; sA[c+1][bb]=v.y*scale;
    sA[c+2][bb]=v.z*scale; sA[c+3][bb]=v.w*scale;
  }
}
__device__ __forceinline__ void p2_loadP(const float* Pptr, int c0,
                                         int strideP, float (*sP)[68], int tid){
  #pragma unroll
  for (int it=0; it<8; it++){
    int u = tid + it*128;
    int kk = u >> 4, cq = u & 15;
    float4 v = *(const float4*)&Pptr[(size_t)kk*strideP + c0 + cq*4];
    int c = cq*4;
    sP[c+0][kk]=v.x; sP[c+1][kk]=v.y; sP[c+2][kk]=v.z; sP[c+3][kk]=v.w;
  }
}
__device__ __forceinline__ void p2_compute(const float (*sA)[20], const float (*sP)[68],
                                           int bg, int kg, float* acc){
  #pragma unroll 8
  for (int c=0;c<64;c++){
    float2 a = *(const float2*)&sA[c][bg*2];
    float4 p = *(const float4*)&sP[c][kg*4];
    acc[0]+=a.x*p.x; acc[1]+=a.x*p.y; acc[2]+=a.x*p.z; acc[3]+=a.x*p.w;
    acc[4]+=a.y*p.x; acc[5]+=a.y*p.y; acc[6]+=a.y*p.z; acc[7]+=a.y*p.w;
  }
}

__global__ __launch_bounds__(128)
void k_phase2(const float* wn_w2, const float* wn_b2, const float* w_raw,
              const float* log_gamma, float* out)
{
  int tid = threadIdx.x;
  int bg = tid >> 4;
  int kg = tid & 15;
  int b0 = blockIdx.x * TB2;

  __shared__ __align__(16) float sA[64][20];
  __shared__ __align__(16) float sP[64][68];
  __shared__ float sHb[TB2][33];
  __shared__ float sHp[KK][33];
  __shared__ float sArad[TB2][19];
  __shared__ float sPrad[KK][19];
  __shared__ float sScB[TB2][5];
  __shared__ float sHpsq[KK];
  __shared__ float sW2[32];

  for (int idx=tid; idx<TB2*32; idx+=128){ int bb=idx>>5, j=idx&31; sHb[bb][j]=g_hb[(size_t)(b0+bb)*32+j]; }
  for (int idx=tid; idx<KK*32; idx+=128){ int kk=idx>>5, j=idx&31; sHp[kk][j]=g_hp[kk*32+j]; }
  for (int idx=tid; idx<TB2*18; idx+=128){ int bb=idx/18, j=idx%18; sArad[bb][j]=g_Arad[(size_t)(b0+bb)*18+j]; }
  for (int idx=tid; idx<KK*18; idx+=128){ int kk=idx/18, j=idx%18; sPrad[kk][j]=g_Prad[kk*18+j]; }
  for (int idx=tid; idx<TB2*5; idx+=128){
    int bb=idx/5, q=idx%5, bgl=b0+bb;
    float v;
    switch(q){
      case 0: v=g_T1feat[bgl]; break;
      case 1: v=g_T1str[bgl];  break;
      case 2: v=g_Srad[bgl];   break;
      case 3: v=g_hrootsq[bgl];break;
      default:v=g_alpha[bgl];
    }
    sScB[bb][q]=v;
  }
  if (tid < KK) sHpsq[tid]=g_hproto_sq[tid];
  if (tid < 32) sW2[tid]=wn_w2[tid];

  float accF[8], accS[8], accR[8];
  #pragma unroll
  for (int q=0;q<8;q++){ accF[q]=0.f; accS[q]=0.f; accR[q]=0.f; }

  for (int ch=0; ch<9; ch++){
    __syncthreads();
    p2_loadA(g_Afeat, b0, ch*64, 576, 1.f, sA, tid);
    p2_loadP(g_Pfeat, ch*64, 576, sP, tid);
    __syncthreads();
    p2_compute(sA, sP, bg, kg, accF);
  }
  for (int ch=0; ch<9; ch++){
    __syncthreads();
    p2_loadA(g_Astr, b0, ch*64, 576, 1.f, sA, tid);
    p2_loadP(g_Pstr, ch*64, 576, sP, tid);
    __syncthreads();
    p2_compute(sA, sP, bg, kg, accS);
  }
  for (int ch=0; ch<2; ch++){
    __syncthreads();
    p2_loadA(g_hroot, b0, ch*64, DXX, -2.f, sA, tid);
    p2_loadP(g_hproto_root, ch*64, DXX, sP, tid);
    __syncthreads();
    p2_compute(sA, sP, bg, kg, accR);
  }

  float accD[8];
  #pragma unroll
  for (int q=0;q<8;q++) accD[q]=0.f;
  #pragma unroll
  for (int j=0;j<18;j++){
    float a0=sArad[bg*2+0][j], a1=sArad[bg*2+1][j];
    float p0=sPrad[kg*4+0][j], p1=sPrad[kg*4+1][j], p2=sPrad[kg*4+2][j], p3=sPrad[kg*4+3][j];
    accD[0]+=a0*p0; accD[1]+=a0*p1; accD[2]+=a0*p2; accD[3]+=a0*p3;
    accD[4]+=a1*p0; accD[5]+=a1*p1; accD[6]+=a1*p2; accD[7]+=a1*p3;
  }

  float wlog[8];
  #pragma unroll
  for (int q=0;q<8;q++) wlog[q]=0.f;
  #pragma unroll 8
  for (int j=0;j<32;j++){
    float w2 = sW2[j];
    float b0v=sHb[bg*2+0][j], b1v=sHb[bg*2+1][j];
    float p0=sHp[kg*4+0][j], p1=sHp[kg*4+1][j], p2=sHp[kg*4+2][j], p3=sHp[kg*4+3][j];
    wlog[0]+=fmaxf(b0v+p0,0.f)*w2; wlog[1]+=fmaxf(b0v+p1,0.f)*w2;
    wlog[2]+=fmaxf(b0v+p2,0.f)*w2; wlog[3]+=fmaxf(b0v+p3,0.f)*w2;
    wlog[4]+=fmaxf(b1v+p0,0.f)*w2; wlog[5]+=fmaxf(b1v+p1,0.f)*w2;
    wlog[6]+=fmaxf(b1v+p2,0.f)*w2; wlog[7]+=fmaxf(b1v+p3,0.f)*w2;
  }

  float wraw = w_raw[0], wb2 = wn_b2[0];
  float gamma = expf(log_gamma[0]);

  #pragma unroll
  for (int i=0;i<2;i++){
    int bi = bg*2+i;
    float T1f=sScB[bi][0], T1s=sScB[bi][1], Sr=sScB[bi][2], hrsq=sScB[bi][3], al=sScB[bi][4];
    float res[4];
    #pragma unroll
    for (int j=0;j<4;j++){
      int q = i*4+j;
      int kk = kg*4+j;
      float wgt = 1.f/(1.f+expf(-(wraw + wlog[q] + wb2)));
      float drf = hrsq + sHpsq[kk] + accR[q];
      float swf = (T1f + accF[q])*(1.f/(float)LL);
      float sws = (T1s + accS[q])*(1.f/(float)LL);
      float rad = Sr + accD[q];
      float df = wgt*drf + (1.f-wgt)*swf;
      float ds = wgt*rad + (1.f-wgt)*sws;
      float dfgw = al*df + (1.f-al)*ds;
      res[j] = expf(-gamma*dfgw);
    }
    *(float4*)&out[(size_t)(b0+bi)*KK + kg*4] = make_float4(res[0],res[1],res[2],res[3]);
  }
}

// ------------------- launcher -------------------
extern "C" void kernel_launch(void* const* d_in, const int* in_sizes, int n_in,
                              void* d_out, int out_size)
{
  const float* adj        = (const float*)d_in[0];
  const float* features   = (const float*)d_in[1];
  const int*   idxs       = (const int*)  d_in[2];
  const float* x_lin_w    = (const float*)d_in[3];
  const float* x_lin_b    = (const float*)d_in[4];
  const float* x_ln_g     = (const float*)d_in[5];
  const float* x_ln_b     = (const float*)d_in[6];
  const float* s_ln_g     = (const float*)d_in[7];
  const float* s_ln_b     = (const float*)d_in[8];
  const float* theta_x    = (const float*)d_in[9];
  const float* theta_s    = (const float*)d_in[10];
  const float* alpha_raw  = (const float*)d_in[11];
  const float* an_w1      = (const float*)d_in[12];
  const float* an_b1      = (const float*)d_in[13];
  const float* an_w2      = (const float*)d_in[14];
  const float* an_b2      = (const float*)d_in[15];
  const float* wn_w1      = (const float*)d_in[16];
  const float* wn_b1      = (const float*)d_in[17];
  const float* wn_w2      = (const float*)d_in[18];
  const float* wn_b2      = (const float*)d_in[19];
  const float* w_raw      = (const float*)d_in[20];
  const float* proto_root = (const float*)d_in[21];
  const float* proto_neigh= (const float*)d_in[22];
  const float* proto_rad  = (const float*)d_in[23];
  const float* proto_dn   = (const float*)d_in[24];
  const float* log_gamma  = (const float*)d_in[25];
  float* out = (float*)d_out;

  cudaFuncSetAttribute(k_lin_mma, cudaFuncAttributeMaxDynamicSharedMemorySize, SMEM_LIN);

  k_tn<<<1,128>>>(theta_x, theta_s);
  k_prep<<<41,256>>>(x_lin_w, x_lin_b, x_ln_g, x_ln_b, an_w1);
  k_prepB<<<192,256>>>();
  k_proto<<<KK,128>>>(x_lin_w, x_lin_b, x_ln_g, x_ln_b, s_ln_g, s_ln_b,
                      wn_w1, proto_root, proto_neigh, proto_rad, proto_dn);
  k_lin_mma<<<(BB*MM)/128, 512, SMEM_LIN>>>(features, idxs);
  k_phase1b<<<BB/8,256>>>(adj, idxs, x_ln_g, x_ln_b, s_ln_g, s_ln_b,
                          an_b1, an_w2, an_b2, wn_w1, wn_b1, alpha_raw);
  k_phase2<<<BB/TB2,128>>>(wn_w2, wn_b2, w_raw, log_gamma, out);
}

// round 10
// speedup vs baseline: 1.4601x; 1.0043x over previous
#include <cuda_runtime.h>
#include <cuda_bf16.h>
#include <math.h>
#include <stdint.h>

#define BB   8192
#define MM   10
#define NNB  9
#define FIN  128
#define DXX  128
#define KK   64
#define LL   32
#define NALL 100000
#define GN   192
#define TB2  16

// ------------------- device scratch -------------------
__device__ float g_tnxT[FIN*LL];
__device__ float g_tnsT[NNB*LL];
__device__ float g_Bmat[FIN*GN];
__device__ float g_biasv[GN];
__device__ float g_cSg[64];
__device__ float g_cCb[64];
__device__ float g_Hraw[(size_t)BB*MM*GN];
__device__ __align__(16) __nv_bfloat16 g_BtileH[2*GN*136];   // [half][n][k_pad136]

__device__ float g_hproto_root[KK*DXX];
__device__ float g_hproto_sq[KK];
__device__ float g_hp[KK*32];
__device__ float g_Pfeat[KK*576];
__device__ float g_Pstr[KK*576];
__device__ float g_Prad[KK*18];

__device__ float g_hroot[BB*DXX];
__device__ float g_hrootsq[BB];
__device__ float g_hb[BB*32];
__device__ float g_alpha[BB];
__device__ float g_Afeat[(size_t)BB*576];
__device__ float g_T1feat[BB];
__device__ float g_Astr[(size_t)BB*576];
__device__ float g_T1str[BB];
__device__ float g_Arad[BB*18];
__device__ float g_Srad[BB];

// ------------------- helpers -------------------
__device__ __forceinline__ void sort9(float* v){
  for (int a=1;a<NNB;a++){
    float x=v[a]; int c=a-1;
    while (c>=0 && v[c]>x){ v[c+1]=v[c]; c--; }
    v[c+1]=x;
  }
}
__device__ __forceinline__ void argsort9(const float* v, int* ord){
  for (int a=0;a<NNB;a++) ord[a]=a;
  for (int a=1;a<NNB;a++){
    int o=ord[a]; float x=v[o]; int c=a-1;
    while (c>=0 && v[ord[c]]>x){ ord[c+1]=ord[c]; c--; }
    ord[c+1]=o;
  }
}
__device__ __forceinline__ float wredsum(float v){
  #pragma unroll
  for (int o=16;o;o>>=1) v += __shfl_xor_sync(0xffffffffu, v, o);
  return v;
}
__device__ __forceinline__ void ln_rows(float (*sH)[FIN], int nrows,
                                        const float* g, const float* b, int t){
  int w = t>>5, lane = t&31;
  for (int r=w; r<nrows; r+=4){
    float s=0.f;
    for (int j=lane;j<FIN;j+=32) s += sH[r][j];
    s = wredsum(s);
    float mu = s*(1.f/FIN);
    float s2=0.f;
    for (int j=lane;j<FIN;j+=32){ float d=sH[r][j]-mu; s2 += d*d; }
    s2 = wredsum(s2);
    float rstd = rsqrtf(s2*(1.f/FIN)+1e-5f);
    for (int j=lane;j<FIN;j+=32) sH[r][j] = (sH[r][j]-mu)*rstd*g[j] + b[j];
  }
}
__device__ __forceinline__ uint32_t smem_u32(const void* p){
  uint32_t a;
  asm("{ .reg .u64 t; cvta.to.shared.u64 t, %1; cvt.u32.u64 %0, t; }" : "=r"(a) : "l"(p));
  return a;
}
// ---- sm_80-compatible tensor core ops ----
__device__ __forceinline__ void ldsm_x4(uint32_t* r, uint32_t addr){
  asm volatile("ldmatrix.sync.aligned.m8n8.x4.shared.b16 {%0,%1,%2,%3}, [%4];"
    : "=r"(r[0]),"=r"(r[1]),"=r"(r[2]),"=r"(r[3]) : "r"(addr));
}
__device__ __forceinline__ void ldsm_x2(uint32_t* r, uint32_t addr){
  asm volatile("ldmatrix.sync.aligned.m8n8.x2.shared.b16 {%0,%1}, [%2];"
    : "=r"(r[0]),"=r"(r[1]) : "r"(addr));
}
__device__ __forceinline__ void mma16816(float* c, const uint32_t* a, const uint32_t* b){
  asm volatile(
    "mma.sync.aligned.m16n8k16.row.col.f32.bf16.bf16.f32 "
    "{%0,%1,%2,%3}, {%4,%5,%6,%7}, {%8,%9}, {%0,%1,%2,%3};"
    : "+f"(c[0]),"+f"(c[1]),"+f"(c[2]),"+f"(c[3])
    : "r"(a[0]),"r"(a[1]),"r"(a[2]),"r"(a[3]), "r"(b[0]),"r"(b[1]));
}

// ------------------- kernel 0: normalize thetas -------------------
__global__ void k_tn(const float* theta_x, const float* theta_s){
  int t = threadIdx.x, w=t>>5, lane=t&31;
  for (int row=w; row<LL; row+=4){
    float s=0.f;
    for (int j=lane;j<FIN;j+=32){ float v=theta_x[row*FIN+j]; s+=v*v; }
    s = wredsum(s);
    float inv = 1.0f/sqrtf(s);
    for (int j=lane;j<FIN;j+=32) g_tnxT[j*LL+row] = theta_x[row*FIN+j]*inv;
  }
  if (t < LL){
    float s=0.f;
    for (int j=0;j<NNB;j++){ float v=theta_s[t*NNB+j]; s+=v*v; }
    float inv = 1.0f/sqrtf(s);
    for (int j=0;j<NNB;j++) g_tnsT[j*LL+t] = theta_s[t*NNB+j]*inv;
  }
}

// ------------------- kernel 0b: build folded B matrix -------------------
__global__ void k_prep(const float* Wlin, const float* blin,
                       const float* lng, const float* lnb,
                       const float* an_w1){
  int bid = blockIdx.x, t = threadIdx.x;
  if (bid < 32){
    int out = bid*256 + t;
    int i = out >> 6, c = out & 63;
    float acc = 0.f;
    for (int d=0; d<FIN; d++){
      float th = (c<32) ? g_tnxT[d*LL + c] : an_w1[d*32 + (c-32)];
      acc += Wlin[i*DXX + d] * (lng[d]*th);
    }
    g_Bmat[i*GN + 128 + c] = acc;
  } else if (bid < 40){
    int base = (bid-32)*2048;
    for (int it=0; it<8; it++){
      int u = base + t + it*256;
      g_Bmat[(u>>7)*GN + (u&127)] = Wlin[u];
    }
  } else {
    if (t < 128) g_biasv[t] = blin[t];
    if (t < 64){
      float bs=0.f, sg=0.f, cb=0.f;
      for (int d=0; d<FIN; d++){
        float th = (t<32) ? g_tnxT[d*LL + t] : an_w1[d*32 + (t-32)];
        float v = lng[d]*th;
        bs += blin[d]*v;
        sg += v;
        cb += lnb[d]*th;
      }
      g_biasv[128+t]=bs; g_cSg[t]=sg; g_cCb[t]=cb;
    }
  }
}

// ------------------- kernel 0c: bf16 hi/lo padded B tiles [half][n][136] -------------------
__global__ void k_prepB(){
  int e = blockIdx.x*256 + threadIdx.x;     // < 49152 = 2*192*128
  int half = e / 24576;
  int r = e % 24576;
  int n = r >> 7, k = r & 127;
  float v = g_Bmat[k*GN + n];
  __nv_bfloat16 hb = __float2bfloat16(v);
  __nv_bfloat16 val = (half==0) ? hb : __float2bfloat16(v - __bfloat162float(hb));
  g_BtileH[(half*GN + n)*136 + k] = val;
}

// ------------------- kernel 2a: split-bf16 mma.sync gathered GEMM (512 thr, 16 warps) ----
#define SM_IDX   0
#define SM_BIAS  512
#define SM_AHI   2048
#define SM_ALO   (SM_AHI + 128*136*2)
#define SM_BHI   (SM_ALO + 128*136*2)
#define SM_BLO   (SM_BHI + 192*136*2)
#define SMEM_LIN (SM_BLO + 192*136*2)      // 176128 bytes
#define STG_STRIDE 196

__global__ __launch_bounds__(512)
void k_lin_mma(const float* features, const int* idxs)
{
  extern __shared__ char smem[];
  int tid = threadIdx.x;
  int wid = tid >> 5, lane = tid & 31;
  size_t row0 = (size_t)blockIdx.x * 128;
  int* sIdx = (int*)(smem + SM_IDX);
  float* sBias = (float*)(smem + SM_BIAS);

  if (tid < 128) sIdx[tid] = idxs[row0 + tid];
  if (tid >= 256 && tid < 448) sBias[tid-256] = g_biasv[tid-256];

  {
    const uint4* src = (const uint4*)g_BtileH;
    uint4* dst = (uint4*)(smem + SM_BHI);
    #pragma unroll
    for (int i=0;i<13;i++){
      int u = tid + i*512;
      if (u < 6528) dst[u] = src[u];
    }
  }
  __syncthreads();

  #pragma unroll
  for (int i=0;i<8;i++){
    int u = tid + i*512;
    int row = u >> 5, q = u & 31;
    int id = sIdx[row];
    float4 v;
    if (id == NALL) v = make_float4(0.f,0.f,0.f,0.f);
    else v = *(const float4*)&features[(size_t)id*FIN + q*4];
    __nv_bfloat162 h01 = __floats2bfloat162_rn(v.x, v.y);
    __nv_bfloat162 h23 = __floats2bfloat162_rn(v.z, v.w);
    float2 f01 = __bfloat1622float2(h01);
    float2 f23 = __bfloat1622float2(h23);
    __nv_bfloat162 l01 = __floats2bfloat162_rn(v.x - f01.x, v.y - f01.y);
    __nv_bfloat162 l23 = __floats2bfloat162_rn(v.z - f23.x, v.w - f23.y);
    uint32_t off = (uint32_t)(row*136 + q*4)*2;
    *(__nv_bfloat162*)(smem + SM_AHI + off)     = h01;
    *(__nv_bfloat162*)(smem + SM_AHI + off + 4) = h23;
    *(__nv_bfloat162*)(smem + SM_ALO + off)     = l01;
    *(__nv_bfloat162*)(smem + SM_ALO + off + 4) = l23;
  }
  __syncthreads();

  int wm = wid >> 1, wn = wid & 1;
  int mbase = wm*16, nbase = wn*96;
  uint32_t sb = smem_u32(smem);

  float acc[12][4];
  #pragma unroll
  for (int j=0;j<12;j++)
    #pragma unroll
    for (int q=0;q<4;q++) acc[j][q]=0.f;

  int aRow = mbase + ((lane>>3)&1)*8 + (lane&7);
  int aK   = (lane>>4)*8;
  int bRow = nbase + (lane&7);
  int bK   = ((lane>>3)&1)*8;

  #pragma unroll
  for (int kc=0; kc<8; kc++){
    uint32_t bf[12][2];
    #pragma unroll
    for (int j=0;j<12;j++)
      ldsm_x2(bf[j], sb + SM_BHI + (uint32_t)((bRow + j*8)*136 + kc*16 + bK)*2);
    uint32_t af[4];
    ldsm_x4(af, sb + SM_AHI + (uint32_t)(aRow*136 + kc*16 + aK)*2);
    #pragma unroll
    for (int j=0;j<12;j++) mma16816(acc[j], af, bf[j]);
    ldsm_x4(af, sb + SM_ALO + (uint32_t)(aRow*136 + kc*16 + aK)*2);
    #pragma unroll
    for (int j=0;j<12;j++) mma16816(acc[j], af, bf[j]);
  }
  #pragma unroll
  for (int kc=0; kc<8; kc++){
    uint32_t bf[12][2];
    #pragma unroll
    for (int j=0;j<12;j++)
      ldsm_x2(bf[j], sb + SM_BLO + (uint32_t)((bRow + j*8)*136 + kc*16 + bK)*2);
    uint32_t af[4];
    ldsm_x4(af, sb + SM_AHI + (uint32_t)(aRow*136 + kc*16 + aK)*2);
    #pragma unroll
    for (int j=0;j<12;j++) mma16816(acc[j], af, bf[j]);
  }
  __syncthreads();

  float* stage = (float*)(smem + SM_AHI);
  {
    int r = lane >> 2, c2 = 2*(lane & 3);
    int rr = mbase + r;
    #pragma unroll
    for (int j=0;j<12;j++){
      int cc = nbase + j*8 + c2;
      float b0 = sBias[cc], b1 = sBias[cc+1];
      *(float2*)&stage[rr*STG_STRIDE + cc]     = make_float2(acc[j][0]+b0, acc[j][1]+b1);
      *(float2*)&stage[(rr+8)*STG_STRIDE + cc] = make_float2(acc[j][2]+b0, acc[j][3]+b1);
    }
  }
  __syncthreads();
  #pragma unroll
  for (int i=0;i<12;i++){
    int u = tid + i*512;
    int row = u/48, q = u%48;
    *(float4*)&g_Hraw[(row0 + row)*GN + q*4] = *(float4*)&stage[row*STG_STRIDE + q*4];
  }
}

// ------------------- fused kernel: blocks [0,1024) phase1b ; [1024,1056) proto (2/block) ----
#define P1B_BLOCKS (BB/8)

__global__ __launch_bounds__(256)
void k_fused(const float* adj, const int* idxs,
             const float* lng, const float* lnb,
             const float* sg, const float* sb,
             const float* an_b1, const float* an_w2, const float* an_b2,
             const float* wn_w1, const float* wn_b1,
             const float* alpha_raw,
             const float* Wlin, const float* blin,
             const float* proto_root, const float* proto_neigh,
             const float* proto_rad, const float* proto_dn)
{
  __shared__ __align__(16) char sBuf[26160];
  int tid = threadIdx.x;

  if (blockIdx.x >= P1B_BLOCKS){
    // ================= proto branch: two protos per block =================
    int h = tid >> 7, tl = tid & 127;
    int k = (blockIdx.x - P1B_BLOCKS)*2 + h;

    float (*sXT)[FIN][12]  = (float(*)[FIN][12])(sBuf);            // 12288
    float (*sH)[MM][FIN]   = (float(*)[MM][FIN])(sBuf + 12288);    // 10240
    float (*sPp)[NNB][LL]  = (float(*)[NNB][LL])(sBuf + 22528);    // 2304
    float (*sC)[NNB][NNB]  = (float(*)[NNB][NNB])(sBuf + 24832);   // 648
    float (*sCS)[NNB][NNB] = (float(*)[NNB][NNB])(sBuf + 25480);   // 648
    float (*sRed)[4]       = (float(*)[4])(sBuf + 26128);          // 32

    sXT[h][tl][0] = proto_root[k*FIN + tl];
    for (int m=0;m<NNB;m++) sXT[h][tl][m+1] = proto_neigh[(k*NNB+m)*FIN + tl];
    __syncthreads();

    float acc[MM];
    {
      float bias = blin[tl];
      #pragma unroll
      for (int r=0;r<MM;r++) acc[r]=bias;
      for (int i=0;i<FIN;i++){
        float wv = Wlin[i*DXX+tl];
        float4 xa = *(const float4*)&sXT[h][i][0];
        float4 xb = *(const float4*)&sXT[h][i][4];
        float2 xc = *(const float2*)&sXT[h][i][8];
        acc[0]+=xa.x*wv; acc[1]+=xa.y*wv; acc[2]+=xa.z*wv; acc[3]+=xa.w*wv;
        acc[4]+=xb.x*wv; acc[5]+=xb.y*wv; acc[6]+=xb.z*wv; acc[7]+=xb.w*wv;
        acc[8]+=xc.x*wv; acc[9]+=xc.y*wv;
      }
    }
    #pragma unroll
    for (int r=0;r<MM;r++) sH[h][r][tl]=acc[r];
    __syncthreads();
    ln_rows(sH[h], MM, lng, lnb, tl);
    __syncthreads();

    g_hproto_root[k*DXX+tl] = sH[h][0][tl];
    {
      float v = sH[h][0][tl]; v*=v;
      v = wredsum(v);
      if ((tl&31)==0) sRed[h][tl>>5]=v;
    }
    __syncthreads();
    if (tl==0) g_hproto_sq[k] = sRed[h][0]+sRed[h][1]+sRed[h][2]+sRed[h][3];
    if (tl<32){
      float v=0.f;
      for (int d=0;d<DXX;d++) v += sH[h][0][d]*wn_w1[(DXX+d)*32 + tl];
      g_hp[k*32+tl]=v;
    }
    for (int q=tl;q<NNB*LL;q+=128){
      int m=q/LL, l=q%LL;
      float v=0.f;
      for (int d=0;d<DXX;d++) v += sH[h][1+m][d]*g_tnxT[d*LL+l];
      sPp[h][m][l]=v;
    }
    __syncthreads();
    if (tl<LL){
      float vals[NNB];
      for (int m=0;m<NNB;m++) vals[m]=sPp[h][m][tl];
      sort9(vals);
      for (int j=0;j<NNB;j++){
        float v=vals[j];
        g_Pfeat[k*576 + j*LL + tl]       = v;
        g_Pfeat[k*576 + 288 + j*LL + tl] = v*v;
      }
    }
    if (tl < 36){
      int p=tl, i=0;
      while (p >= NNB-1-i){ p -= NNB-1-i; i++; }
      int j = i+1+p;
      float x = proto_dn[tl*KK + k];
      float s = 1.0f/(1.0f+expf(-x));
      sC[h][i][j]=s; sC[h][j][i]=s;
    }
    if (tl < NNB) sC[h][tl][tl]=0.f;
    __syncthreads();
    if (tl < NNB){
      float c[NNB];
      for (int i=0;i<NNB;i++) c[i]=sC[h][i][tl];
      sort9(c);
      for (int i=0;i<NNB;i++) sCS[h][i][tl]=c[i];
    }
    __syncthreads();
    if (tl < NNB){
      float mu=0.f; for(int j=0;j<NNB;j++) mu+=sCS[h][tl][j]; mu*=(1.f/NNB);
      float var=0.f; for(int j=0;j<NNB;j++){float d=sCS[h][tl][j]-mu; var+=d*d;} var*=(1.f/NNB);
      float rstd = rsqrtf(var+1e-5f);
      for (int j=0;j<NNB;j++) sCS[h][tl][j] = (sCS[h][tl][j]-mu)*rstd*sg[j]+sb[j];
    }
    __syncthreads();
    if (tl<LL){
      float vals[NNB];
      for (int m=0;m<NNB;m++){
        float v=0.f;
        for (int j=0;j<NNB;j++) v += sCS[h][m][j]*g_tnsT[j*LL+tl];
        vals[m]=v;
      }
      sort9(vals);
      for (int j=0;j<NNB;j++){
        float v=vals[j];
        g_Pstr[k*576 + j*LL + tl]       = v;
        g_Pstr[k*576 + 288 + j*LL + tl] = v*v;
      }
    }
    if (tl==0){
      float r[NNB];
      for (int j=0;j<NNB;j++) r[j]=proto_rad[k*NNB+j];
      sort9(r);
      for (int j=0;j<NNB;j++){ g_Prad[k*18+j]=r[j]; g_Prad[k*18+9+j]=r[j]*r[j]; }
    }
    return;
  }

  // ================= phase1b branch: warp-per-b =================
  int w = tid >> 5, lane = tid & 31;
  int b = blockIdx.x*8 + w;

  float (*sDm)[MM][MM]   = (float(*)[MM][MM])(sBuf);               // 3200
  float (*sHS)[NNB][NNB] = (float(*)[NNB][NNB])(sBuf + 3200);      // 2592
  float (*sHn)[FIN]      = (float(*)[FIN])(sBuf + 5792);           // 4096
  float (*sVm)[NNB]      = (float(*)[NNB])(sBuf + 9888);           // 288
  unsigned (*sNbr)[MM]   = (unsigned(*)[MM])(sBuf + 10176);        // 320
  float (*sTnsT)[32]     = (float(*)[32])(sBuf + 10496);           // 1152

  for (int u=tid; u<NNB*32; u+=256) sTnsT[u>>5][u&31] = g_tnsT[u];

  const float* HR = g_Hraw + (size_t)b*MM*GN;

  if (lane < MM){
    int idv = idxs[b*MM + lane];
    if (lane >= 1) sVm[w][lane-1] = (idv != NALL) ? 1.f : 0.f;
    unsigned nb=0;
    const float* arow = adj + (size_t)b*MM*MM + lane*MM;
    #pragma unroll
    for (int j=0;j<MM;j++) if (arow[j] > 1e-5f) nb |= (1u<<j);
    sNbr[w][lane]=nb;
  }
  __syncthreads();

  float vs = 0.f;
  #pragma unroll
  for (int j=0;j<NNB;j++) vs += sVm[w][j];
  float vsi = 1.f/(vs + 1e-9f);

  if (lane < MM){
    float drow[MM];
    #pragma unroll
    for (int j=0;j<MM;j++) drow[j] = (j==lane)?0.f:10.f;
    unsigned reach = 1u<<lane, frontier = 1u<<lane;
    for (int step=1; step<MM; step++){
      unsigned nxt=0;
      #pragma unroll
      for (int v=0;v<MM;v++) if (frontier & (1u<<v)) nxt |= sNbr[w][v];
      nxt &= ~reach;
      if (!nxt) break;
      #pragma unroll
      for (int v=0;v<MM;v++) if (nxt & (1u<<v)) drow[v]=(float)step;
      reach |= nxt; frontier = nxt;
    }
    #pragma unroll
    for (int j=0;j<MM;j++) sDm[w][lane][j]=drow[j];
  }
  __syncwarp();
  for (int q=lane; q<MM*MM; q+=32){
    int i=q/MM, j=q%MM;
    float fi = (i==0)?1.f:sVm[w][i-1];
    float fj = (j==0)?1.f:sVm[w][j-1];
    sDm[w][i][j] = (fi*fj>0.f) ? sDm[w][i][j]*0.1f : 1.0f;
  }
  __syncwarp();

  float lg0=lng[lane], lg1=lng[lane+32], lg2=lng[lane+64], lg3=lng[lane+96];
  float lb0=lnb[lane], lb1=lnb[lane+32], lb2=lnb[lane+64], lb3=lnb[lane+96];
  {
    float a0=HR[lane], a1=HR[lane+32], a2=HR[lane+64], a3=HR[lane+96];
    float s = wredsum(a0+a1+a2+a3);
    float mu = s*(1.f/FIN);
    float d0=a0-mu,d1=a1-mu,d2=a2-mu,d3=a3-mu;
    float s2 = wredsum(d0*d0+d1*d1+d2*d2+d3*d3);
    float rs = rsqrtf(s2*(1.f/FIN)+1e-5f);
    float h0=d0*rs*lg0+lb0, h1=d1*rs*lg1+lb1, h2=d2*rs*lg2+lb2, h3=d3*rs*lg3+lb3;
    sHn[w][lane]=h0; sHn[w][lane+32]=h1; sHn[w][lane+64]=h2; sHn[w][lane+96]=h3;
    g_hroot[(size_t)b*DXX+lane]=h0; g_hroot[(size_t)b*DXX+lane+32]=h1;
    g_hroot[(size_t)b*DXX+lane+64]=h2; g_hroot[(size_t)b*DXX+lane+96]=h3;
    float qq = wredsum(h0*h0+h1*h1+h2*h2+h3*h3);
    if (lane==0) g_hrootsq[b]=qq;
  }
  float muv[NNB], rsv[NNB];
  #pragma unroll
  for (int r=1; r<MM; r++){
    const float* Hr = HR + r*GN;
    float a0=Hr[lane], a1=Hr[lane+32], a2=Hr[lane+64], a3=Hr[lane+96];
    float s = wredsum(a0+a1+a2+a3);
    float mu = s*(1.f/FIN);
    float d0=a0-mu,d1=a1-mu,d2=a2-mu,d3=a3-mu;
    float s2 = wredsum(d0*d0+d1*d1+d2*d2+d3*d3);
    muv[r-1]=mu; rsv[r-1]=rsqrtf(s2*(1.f/FIN)+1e-5f);
  }
  __syncwarp();

  if (lane < NNB){
    float c[NNB];
    #pragma unroll
    for (int i=0;i<NNB;i++) c[i]=sDm[w][1+i][1+lane];
    sort9(c);
    #pragma unroll
    for (int i=0;i<NNB;i++) sHS[w][i][lane]=c[i];
  }
  __syncwarp();
  if (lane < NNB){
    float mu=0.f;
    #pragma unroll
    for (int j=0;j<NNB;j++) mu+=sHS[w][lane][j];
    mu *= (1.f/NNB);
    float var=0.f;
    #pragma unroll
    for (int j=0;j<NNB;j++){ float d=sHS[w][lane][j]-mu; var+=d*d; }
    var *= (1.f/NNB);
    float rstd=rsqrtf(var+1e-5f);
    #pragma unroll
    for (int j=0;j<NNB;j++) sHS[w][lane][j]=(sHS[w][lane][j]-mu)*rstd*sg[j]+sb[j];
  }
  __syncwarp();

  {
    float cSgl=g_cSg[lane], cCbl=g_cCb[lane];
    float vals[NNB]; int ord[NNB];
    #pragma unroll
    for (int m=0;m<NNB;m++)
      vals[m] = rsv[m]*(HR[(1+m)*GN+128+lane] - muv[m]*cSgl) + cCbl;
    argsort9(vals, ord);
    float t1=0.f;
    #pragma unroll
    for (int j=0;j<NNB;j++){
      int mo=ord[j];
      float wv = sVm[w][mo]*vsi;
      float pv = vals[mo];
      g_Afeat[(size_t)b*576 + j*LL + lane]       = -2.f*wv*pv;
      g_Afeat[(size_t)b*576 + 288 + j*LL + lane] = wv;
      t1 += wv*pv*pv;
    }
    t1 = wredsum(t1);
    if (lane==0) g_T1feat[b]=t1;
  }
  {
    float vals[NNB]; int ord[NNB];
    #pragma unroll
    for (int m=0;m<NNB;m++){
      float v2=0.f;
      #pragma unroll
      for (int j=0;j<NNB;j++) v2 += sHS[w][m][j]*sTnsT[j][lane];
      vals[m]=v2;
    }
    argsort9(vals, ord);
    float t1=0.f;
    #pragma unroll
    for (int j=0;j<NNB;j++){
      int mo=ord[j];
      float wv = sVm[w][mo]*vsi;
      float pv = vals[mo];
      g_Astr[(size_t)b*576 + j*LL + lane]       = -2.f*wv*pv;
      g_Astr[(size_t)b*576 + 288 + j*LL + lane] = wv;
      t1 += wv*pv*pv;
    }
    t1 = wredsum(t1);
    if (lane==0) g_T1str[b]=t1;
  }
  if (lane==0){
    float rb[NNB]; int ord[NNB];
    #pragma unroll
    for (int j=0;j<NNB;j++) rb[j]=sDm[w][0][1+j];
    argsort9(rb, ord);
    float S=0.f;
    #pragma unroll
    for (int j=0;j<NNB;j++){
      int mo=ord[j];
      float wv=sVm[w][mo]*vsi;
      float v=rb[mo];
      g_Arad[(size_t)b*18+j]   = -2.f*wv*v;
      g_Arad[(size_t)b*18+9+j] = wv;
      S += wv*v*v;
    }
    g_Srad[b]=S;
  }
  {
    float v0 = wn_b1[lane], v1=0.f, v2=0.f, v3=0.f;
    #pragma unroll 8
    for (int d=0; d<DXX; d+=4){
      v0 += sHn[w][d+0]*wn_w1[(d+0)*32+lane];
      v1 += sHn[w][d+1]*wn_w1[(d+1)*32+lane];
      v2 += sHn[w][d+2]*wn_w1[(d+2)*32+lane];
      v3 += sHn[w][d+3]*wn_w1[(d+3)*32+lane];
    }
    g_hb[(size_t)b*32+lane] = (v0+v1)+(v2+v3);
  }
  {
    float cSga=g_cSg[32+lane], cCba=g_cCb[32+lane];
    float s=0.f;
    #pragma unroll
    for (int m=0;m<NNB;m++){
      float av = rsv[m]*(HR[(1+m)*GN+160+lane] - muv[m]*cSga) + cCba;
      s += sVm[w][m]*av;
    }
    float hid = fmaxf(an_b1[lane] + s*vsi, 0.f);
    float vv = wredsum(hid*an_w2[lane]);
    if (lane==0)
      g_alpha[b] = 1.0f/(1.0f+expf(-(alpha_raw[0] + vv + an_b2[0])));
  }
}

// ------------------- kernel 3: register-tiled combine -------------------
__device__ __forceinline__ void p2_loadA(const float* Aptr, int b0, int c0,
                                         int strideA, float scale,
                                         float (*sA)[20], int tid){
  #pragma unroll
  for (int it=0; it<2; it++){
    int u = tid + it*128;
    int bb = u >> 4, cq = u & 15;
    float4 v = *(const float4*)&Aptr[(size_t)(b0+bb)*strideA + c0 + cq*4];
    int c = cq*4;
    sA[c+0][bb]=v.x*scale; sA[c+1][bb]=v.y*scale;
    sA[c+2][bb]=v.z*scale; sA[c+3][bb]=v.w*scale;
  }
}
__device__ __forceinline__ void p2_loadP(const float* Pptr, int c0,
                                         int strideP, float (*sP)[68], int tid){
  #pragma unroll
  for (int it=0; it<8; it++){
    int u = tid + it*128;
    int kk = u >> 4, cq = u & 15;
    float4 v = *(const float4*)&Pptr[(size_t)kk*strideP + c0 + cq*4];
    int c = cq*4;
    sP[c+0][kk]=v.x; sP[c+1][kk]=v.y; sP[c+2][kk]=v.z; sP[c+3][kk]=v.w;
  }
}
__device__ __forceinline__ void p2_compute(const float (*sA)[20], const float (*sP)[68],
                                           int bg, int kg, float* acc){
  #pragma unroll 8
  for (int c=0;c<64;c++){
    float2 a = *(const float2*)&sA[c][bg*2];
    float4 p = *(const float4*)&sP[c][kg*4];
    acc[0]+=a.x*p.x; acc[1]+=a.x*p.y; acc[2]+=a.x*p.z; acc[3]+=a.x*p.w;
    acc[4]+=a.y*p.x; acc[5]+=a.y*p.y; acc[6]+=a.y*p.z; acc[7]+=a.y*p.w;
  }
}

__global__ __launch_bounds__(128)
void k_phase2(const float* wn_w2, const float* wn_b2, const float* w_raw,
              const float* log_gamma, float* out)
{
  int tid = threadIdx.x;
  int bg = tid >> 4;
  int kg = tid & 15;
  int b0 = blockIdx.x * TB2;

  __shared__ __align__(16) float sA[64][20];
  __shared__ __align__(16) float sP[64][68];
  __shared__ float sHb[TB2][33];
  __shared__ float sHp[KK][33];
  __shared__ float sArad[TB2][19];
  __shared__ float sPrad[KK][19];
  __shared__ float sScB[TB2][5];
  __shared__ float sHpsq[KK];
  __shared__ float sW2[32];

  for (int idx=tid; idx<TB2*32; idx+=128){ int bb=idx>>5, j=idx&31; sHb[bb][j]=g_hb[(size_t)(b0+bb)*32+j]; }
  for (int idx=tid; idx<KK*32; idx+=128){ int kk=idx>>5, j=idx&31; sHp[kk][j]=g_hp[kk*32+j]; }
  for (int idx=tid; idx<TB2*18; idx+=128){ int bb=idx/18, j=idx%18; sArad[bb][j]=g_Arad[(size_t)(b0+bb)*18+j]; }
  for (int idx=tid; idx<KK*18; idx+=128){ int kk=idx/18, j=idx%18; sPrad[kk][j]=g_Prad[kk*18+j]; }
  for (int idx=tid; idx<TB2*5; idx+=128){
    int bb=idx/5, q=idx%5, bgl=b0+bb;
    float v;
    switch(q){
      case 0: v=g_T1feat[bgl]; break;
      case 1: v=g_T1str[bgl];  break;
      case 2: v=g_Srad[bgl];   break;
      case 3: v=g_hrootsq[bgl];break;
      default:v=g_alpha[bgl];
    }
    sScB[bb][q]=v;
  }
  if (tid < KK) sHpsq[tid]=g_hproto_sq[tid];
  if (tid < 32) sW2[tid]=wn_w2[tid];

  float accF[8], accS[8], accR[8];
  #pragma unroll
  for (int q=0;q<8;q++){ accF[q]=0.f; accS[q]=0.f; accR[q]=0.f; }

  for (int ch=0; ch<9; ch++){
    __syncthreads();
    p2_loadA(g_Afeat, b0, ch*64, 576, 1.f, sA, tid);
    p2_loadP(g_Pfeat, ch*64, 576, sP, tid);
    __syncthreads();
    p2_compute(sA, sP, bg, kg, accF);
  }
  for (int ch=0; ch<9; ch++){
    __syncthreads();
    p2_loadA(g_Astr, b0, ch*64, 576, 1.f, sA, tid);
    p2_loadP(g_Pstr, ch*64, 576, sP, tid);
    __syncthreads();
    p2_compute(sA, sP, bg, kg, accS);
  }
  for (int ch=0; ch<2; ch++){
    __syncthreads();
    p2_loadA(g_hroot, b0, ch*64, DXX, -2.f, sA, tid);
    p2_loadP(g_hproto_root, ch*64, DXX, sP, tid);
    __syncthreads();
    p2_compute(sA, sP, bg, kg, accR);
  }

  float accD[8];
  #pragma unroll
  for (int q=0;q<8;q++) accD[q]=0.f;
  #pragma unroll
  for (int j=0;j<18;j++){
    float a0=sArad[bg*2+0][j], a1=sArad[bg*2+1][j];
    float p0=sPrad[kg*4+0][j], p1=sPrad[kg*4+1][j], p2=sPrad[kg*4+2][j], p3=sPrad[kg*4+3][j];
    accD[0]+=a0*p0; accD[1]+=a0*p1; accD[2]+=a0*p2; accD[3]+=a0*p3;
    accD[4]+=a1*p0; accD[5]+=a1*p1; accD[6]+=a1*p2; accD[7]+=a1*p3;
  }

  float wlog[8];
  #pragma unroll
  for (int q=0;q<8;q++) wlog[q]=0.f;
  #pragma unroll 8
  for (int j=0;j<32;j++){
    float w2 = sW2[j];
    float b0v=sHb[bg*2+0][j], b1v=sHb[bg*2+1][j];
    float p0=sHp[kg*4+0][j], p1=sHp[kg*4+1][j], p2=sHp[kg*4+2][j], p3=sHp[kg*4+3][j];
    wlog[0]+=fmaxf(b0v+p0,0.f)*w2; wlog[1]+=fmaxf(b0v+p1,0.f)*w2;
    wlog[2]+=fmaxf(b0v+p2,0.f)*w2; wlog[3]+=fmaxf(b0v+p3,0.f)*w2;
    wlog[4]+=fmaxf(b1v+p0,0.f)*w2; wlog[5]+=fmaxf(b1v+p1,0.f)*w2;
    wlog[6]+=fmaxf(b1v+p2,0.f)*w2; wlog[7]+=fmaxf(b1v+p3,0.f)*w2;
  }

  float wraw = w_raw[0], wb2 = wn_b2[0];
  float gamma = expf(log_gamma[0]);

  #pragma unroll
  for (int i=0;i<2;i++){
    int bi = bg*2+i;
    float T1f=sScB[bi][0], T1s=sScB[bi][1], Sr=sScB[bi][2], hrsq=sScB[bi][3], al=sScB[bi][4];
    float res[4];
    #pragma unroll
    for (int j=0;j<4;j++){
      int q = i*4+j;
      int kk = kg*4+j;
      float wgt = 1.f/(1.f+expf(-(wraw + wlog[q] + wb2)));
      float drf = hrsq + sHpsq[kk] + accR[q];
      float swf = (T1f + accF[q])*(1.f/(float)LL);
      float sws = (T1s + accS[q])*(1.f/(float)LL);
      float rad = Sr + accD[q];
      float df = wgt*drf + (1.f-wgt)*swf;
      float ds = wgt*rad + (1.f-wgt)*sws;
      float dfgw = al*df + (1.f-al)*ds;
      res[j] = expf(-gamma*dfgw);
    }
    *(float4*)&out[(size_t)(b0+bi)*KK + kg*4] = make_float4(res[0],res[1],res[2],res[3]);
  }
}

// ------------------- launcher -------------------
extern "C" void kernel_launch(void* const* d_in, const int* in_sizes, int n_in,
                              void* d_out, int out_size)
{
  const float* adj        = (const float*)d_in[0];
  const float* features   = (const float*)d_in[1];
  const int*   idxs       = (const int*)  d_in[2];
  const float* x_lin_w    = (const float*)d_in[3];
  const float* x_lin_b    = (const float*)d_in[4];
  const float* x_ln_g     = (const float*)d_in[5];
  const float* x_ln_b     = (const float*)d_in[6];
  const float* s_ln_g     = (const float*)d_in[7];
  const float* s_ln_b     = (const float*)d_in[8];
  const float* theta_x    = (const float*)d_in[9];
  const float* theta_s    = (const float*)d_in[10];
  const float* alpha_raw  = (const float*)d_in[11];
  const float* an_w1      = (const float*)d_in[12];
  const float* an_b1      = (const float*)d_in[13];
  const float* an_w2      = (const float*)d_in[14];
  const float* an_b2      = (const float*)d_in[15];
  const float* wn_w1      = (const float*)d_in[16];
  const float* wn_b1      = (const float*)d_in[17];
  const float* wn_w2      = (const float*)d_in[18];
  const float* wn_b2      = (const float*)d_in[19];
  const float* w_raw      = (const float*)d_in[20];
  const float* proto_root = (const float*)d_in[21];
  const float* proto_neigh= (const float*)d_in[22];
  const float* proto_rad  = (const float*)d_in[23];
  const float* proto_dn   = (const float*)d_in[24];
  const float* log_gamma  = (const float*)d_in[25];
  float* out = (float*)d_out;

  cudaFuncSetAttribute(k_lin_mma, cudaFuncAttributeMaxDynamicSharedMemorySize, SMEM_LIN);

  k_tn<<<1,128>>>(theta_x, theta_s);
  k_prep<<<41,256>>>(x_lin_w, x_lin_b, x_ln_g, x_ln_b, an_w1);
  k_prepB<<<192,256>>>();
  k_lin_mma<<<(BB*MM)/128, 512, SMEM_LIN>>>(features, idxs);
  k_fused<<<BB/8 + KK/2, 256>>>(adj, idxs, x_ln_g, x_ln_b, s_ln_g, s_ln_b,
                                an_b1, an_w2, an_b2, wn_w1, wn_b1, alpha_raw,
                                x_lin_w, x_lin_b, proto_root, proto_neigh,
                                proto_rad, proto_dn);
  k_phase2<<<BB/TB2,128>>>(wn_w2, wn_b2, w_raw, log_gamma, out);
}

// round 11
// speedup vs baseline: 1.5269x; 1.0457x over previous
#include <cuda_runtime.h>
#include <cuda_bf16.h>
#include <math.h>
#include <stdint.h>

#define BB   8192
#define MM   10
#define NNB  9
#define FIN  128
#define DXX  128
#define KK   64
#define LL   32
#define NALL 100000
#define GN   192
#define TB2  16

// ------------------- device scratch -------------------
__device__ float g_tnxT[FIN*LL];
__device__ float g_tnsT[NNB*LL];
__device__ float g_Bmat[FIN*GN];
__device__ float g_biasv[GN];
__device__ float g_cSg[64];
__device__ float g_cCb[64];
__device__ float g_Hraw[(size_t)BB*MM*GN];
__device__ __align__(16) __nv_bfloat16 g_BtileH[2*GN*136];   // [half][n][k_pad136]

__device__ float g_hproto_root[KK*DXX];
__device__ float g_hproto_sq[KK];
__device__ float g_hp[KK*32];
__device__ float g_Pfeat[KK*576];
__device__ float g_Pstr[KK*576];
__device__ float g_Prad[KK*18];

__device__ float g_hroot[BB*DXX];
__device__ float g_hrootsq[BB];
__device__ float g_hb[BB*32];
__device__ float g_alpha[BB];
__device__ float g_Afeat[(size_t)BB*576];
__device__ float g_T1feat[BB];
__device__ float g_Astr[(size_t)BB*576];
__device__ float g_T1str[BB];
__device__ float g_Arad[BB*18];
__device__ float g_Srad[BB];

// ------------------- helpers -------------------
__device__ __forceinline__ void sort9(float* v){
  for (int a=1;a<NNB;a++){
    float x=v[a]; int c=a-1;
    while (c>=0 && v[c]>x){ v[c+1]=v[c]; c--; }
    v[c+1]=x;
  }
}
__device__ __forceinline__ void argsort9(const float* v, int* ord){
  for (int a=0;a<NNB;a++) ord[a]=a;
  for (int a=1;a<NNB;a++){
    int o=ord[a]; float x=v[o]; int c=a-1;
    while (c>=0 && v[ord[c]]>x){ ord[c+1]=ord[c]; c--; }
    ord[c+1]=o;
  }
}
__device__ __forceinline__ float wredsum(float v){
  #pragma unroll
  for (int o=16;o;o>>=1) v += __shfl_xor_sync(0xffffffffu, v, o);
  return v;
}
__device__ __forceinline__ void ln_rows(float (*sH)[FIN], int nrows,
                                        const float* g, const float* b, int t){
  int w = t>>5, lane = t&31;
  for (int r=w; r<nrows; r+=4){
    float s=0.f;
    for (int j=lane;j<FIN;j+=32) s += sH[r][j];
    s = wredsum(s);
    float mu = s*(1.f/FIN);
    float s2=0.f;
    for (int j=lane;j<FIN;j+=32){ float d=sH[r][j]-mu; s2 += d*d; }
    s2 = wredsum(s2);
    float rstd = rsqrtf(s2*(1.f/FIN)+1e-5f);
    for (int j=lane;j<FIN;j+=32) sH[r][j] = (sH[r][j]-mu)*rstd*g[j] + b[j];
  }
}
__device__ __forceinline__ uint32_t smem_u32(const void* p){
  uint32_t a;
  asm("{ .reg .u64 t; cvta.to.shared.u64 t, %1; cvt.u32.u64 %0, t; }" : "=r"(a) : "l"(p));
  return a;
}
// ---- sm_80-compatible tensor core ops ----
__device__ __forceinline__ void ldsm_x4(uint32_t* r, uint32_t addr){
  asm volatile("ldmatrix.sync.aligned.m8n8.x4.shared.b16 {%0,%1,%2,%3}, [%4];"
    : "=r"(r[0]),"=r"(r[1]),"=r"(r[2]),"=r"(r[3]) : "r"(addr));
}
__device__ __forceinline__ void ldsm_x2(uint32_t* r, uint32_t addr){
  asm volatile("ldmatrix.sync.aligned.m8n8.x2.shared.b16 {%0,%1}, [%2];"
    : "=r"(r[0]),"=r"(r[1]) : "r"(addr));
}
__device__ __forceinline__ void mma16816(float* c, const uint32_t* a, const uint32_t* b){
  asm volatile(
    "mma.sync.aligned.m16n8k16.row.col.f32.bf16.bf16.f32 "
    "{%0,%1,%2,%3}, {%4,%5,%6,%7}, {%8,%9}, {%0,%1,%2,%3};"
    : "+f"(c[0]),"+f"(c[1]),"+f"(c[2]),"+f"(c[3])
    : "r"(a[0]),"r"(a[1]),"r"(a[2]),"r"(a[3]), "r"(b[0]),"r"(b[1]));
}

// ------------------- kernel 0: normalize thetas -------------------
__global__ void k_tn(const float* theta_x, const float* theta_s){
  int t = threadIdx.x, w=t>>5, lane=t&31;
  for (int row=w; row<LL; row+=4){
    float s=0.f;
    for (int j=lane;j<FIN;j+=32){ float v=theta_x[row*FIN+j]; s+=v*v; }
    s = wredsum(s);
    float inv = 1.0f/sqrtf(s);
    for (int j=lane;j<FIN;j+=32) g_tnxT[j*LL+row] = theta_x[row*FIN+j]*inv;
  }
  if (t < LL){
    float s=0.f;
    for (int j=0;j<NNB;j++){ float v=theta_s[t*NNB+j]; s+=v*v; }
    float inv = 1.0f/sqrtf(s);
    for (int j=0;j<NNB;j++) g_tnsT[j*LL+t] = theta_s[t*NNB+j]*inv;
  }
}

// ------------------- kernel 0b: build folded B matrix -------------------
__global__ void k_prep(const float* Wlin, const float* blin,
                       const float* lng, const float* lnb,
                       const float* an_w1){
  int bid = blockIdx.x, t = threadIdx.x;
  if (bid < 32){
    int out = bid*256 + t;
    int i = out >> 6, c = out & 63;
    float acc = 0.f;
    for (int d=0; d<FIN; d++){
      float th = (c<32) ? g_tnxT[d*LL + c] : an_w1[d*32 + (c-32)];
      acc += Wlin[i*DXX + d] * (lng[d]*th);
    }
    g_Bmat[i*GN + 128 + c] = acc;
  } else if (bid < 40){
    int base = (bid-32)*2048;
    for (int it=0; it<8; it++){
      int u = base + t + it*256;
      g_Bmat[(u>>7)*GN + (u&127)] = Wlin[u];
    }
  } else {
    if (t < 128) g_biasv[t] = blin[t];
    if (t < 64){
      float bs=0.f, sg=0.f, cb=0.f;
      for (int d=0; d<FIN; d++){
        float th = (t<32) ? g_tnxT[d*LL + t] : an_w1[d*32 + (t-32)];
        float v = lng[d]*th;
        bs += blin[d]*v;
        sg += v;
        cb += lnb[d]*th;
      }
      g_biasv[128+t]=bs; g_cSg[t]=sg; g_cCb[t]=cb;
    }
  }
}

// ------------------- kernel 0c: bf16 hi/lo padded B tiles [half][n][136] -------------------
__global__ void k_prepB(){
  int e = blockIdx.x*256 + threadIdx.x;     // < 49152 = 2*192*128
  int half = e / 24576;
  int r = e % 24576;
  int n = r >> 7, k = r & 127;
  float v = g_Bmat[k*GN + n];
  __nv_bfloat16 hb = __float2bfloat16(v);
  __nv_bfloat16 val = (half==0) ? hb : __float2bfloat16(v - __bfloat162float(hb));
  g_BtileH[(half*GN + n)*136 + k] = val;
}

// ------------------- kernel 2a: split-bf16 mma.sync gathered GEMM (512 thr, 16 warps) ----
#define SM_IDX   0
#define SM_BIAS  512
#define SM_AHI   2048
#define SM_ALO   (SM_AHI + 128*136*2)
#define SM_BHI   (SM_ALO + 128*136*2)
#define SM_BLO   (SM_BHI + 192*136*2)
#define SMEM_LIN (SM_BLO + 192*136*2)      // 176128 bytes
#define STG_STRIDE 196

__global__ __launch_bounds__(512)
void k_lin_mma(const float* features, const int* idxs)
{
  extern __shared__ char smem[];
  int tid = threadIdx.x;
  int wid = tid >> 5, lane = tid & 31;
  size_t row0 = (size_t)blockIdx.x * 128;
  int* sIdx = (int*)(smem + SM_IDX);
  float* sBias = (float*)(smem + SM_BIAS);

  if (tid < 128) sIdx[tid] = idxs[row0 + tid];
  if (tid >= 256 && tid < 448) sBias[tid-256] = g_biasv[tid-256];

  {
    const uint4* src = (const uint4*)g_BtileH;
    uint4* dst = (uint4*)(smem + SM_BHI);
    #pragma unroll
    for (int i=0;i<13;i++){
      int u = tid + i*512;
      if (u < 6528) dst[u] = src[u];
    }
  }
  __syncthreads();

  #pragma unroll
  for (int i=0;i<8;i++){
    int u = tid + i*512;
    int row = u >> 5, q = u & 31;
    int id = sIdx[row];
    float4 v;
    if (id == NALL) v = make_float4(0.f,0.f,0.f,0.f);
    else v = *(const float4*)&features[(size_t)id*FIN + q*4];
    __nv_bfloat162 h01 = __floats2bfloat162_rn(v.x, v.y);
    __nv_bfloat162 h23 = __floats2bfloat162_rn(v.z, v.w);
    float2 f01 = __bfloat1622float2(h01);
    float2 f23 = __bfloat1622float2(h23);
    __nv_bfloat162 l01 = __floats2bfloat162_rn(v.x - f01.x, v.y - f01.y);
    __nv_bfloat162 l23 = __floats2bfloat162_rn(v.z - f23.x, v.w - f23.y);
    uint32_t off = (uint32_t)(row*136 + q*4)*2;
    *(__nv_bfloat162*)(smem + SM_AHI + off)     = h01;
    *(__nv_bfloat162*)(smem + SM_AHI + off + 4) = h23;
    *(__nv_bfloat162*)(smem + SM_ALO + off)     = l01;
    *(__nv_bfloat162*)(smem + SM_ALO + off + 4) = l23;
  }
  __syncthreads();

  int wm = wid >> 1, wn = wid & 1;
  int mbase = wm*16, nbase = wn*96;
  uint32_t sb = smem_u32(smem);

  float acc[12][4];
  #pragma unroll
  for (int j=0;j<12;j++)
    #pragma unroll
    for (int q=0;q<4;q++) acc[j][q]=0.f;

  int aRow = mbase + ((lane>>3)&1)*8 + (lane&7);
  int aK   = (lane>>4)*8;
  int bRow = nbase + (lane&7);
  int bK   = ((lane>>3)&1)*8;

  #pragma unroll
  for (int kc=0; kc<8; kc++){
    uint32_t bf[12][2];
    #pragma unroll
    for (int j=0;j<12;j++)
      ldsm_x2(bf[j], sb + SM_BHI + (uint32_t)((bRow + j*8)*136 + kc*16 + bK)*2);
    uint32_t af[4];
    ldsm_x4(af, sb + SM_AHI + (uint32_t)(aRow*136 + kc*16 + aK)*2);
    #pragma unroll
    for (int j=0;j<12;j++) mma16816(acc[j], af, bf[j]);
    ldsm_x4(af, sb + SM_ALO + (uint32_t)(aRow*136 + kc*16 + aK)*2);
    #pragma unroll
    for (int j=0;j<12;j++) mma16816(acc[j], af, bf[j]);
  }
  #pragma unroll
  for (int kc=0; kc<8; kc++){
    uint32_t bf[12][2];
    #pragma unroll
    for (int j=0;j<12;j++)
      ldsm_x2(bf[j], sb + SM_BLO + (uint32_t)((bRow + j*8)*136 + kc*16 + bK)*2);
    uint32_t af[4];
    ldsm_x4(af, sb + SM_AHI + (uint32_t)(aRow*136 + kc*16 + aK)*2);
    #pragma unroll
    for (int j=0;j<12;j++) mma16816(acc[j], af, bf[j]);
  }
  __syncthreads();

  float* stage = (float*)(smem + SM_AHI);
  {
    int r = lane >> 2, c2 = 2*(lane & 3);
    int rr = mbase + r;
    #pragma unroll
    for (int j=0;j<12;j++){
      int cc = nbase + j*8 + c2;
      float b0 = sBias[cc], b1 = sBias[cc+1];
      *(float2*)&stage[rr*STG_STRIDE + cc]     = make_float2(acc[j][0]+b0, acc[j][1]+b1);
      *(float2*)&stage[(rr+8)*STG_STRIDE + cc] = make_float2(acc[j][2]+b0, acc[j][3]+b1);
    }
  }
  __syncthreads();
  #pragma unroll
  for (int i=0;i<12;i++){
    int u = tid + i*512;
    int row = u/48, q = u%48;
    *(float4*)&g_Hraw[(row0 + row)*GN + q*4] = *(float4*)&stage[row*STG_STRIDE + q*4];
  }
}

// ------------------- fused kernel: blocks [0,32) proto (2/block, scheduled FIRST);
//                     blocks [32, 32+1024) phase1b warp-per-b ----
#define PROTO_BLOCKS (KK/2)

__global__ __launch_bounds__(256)
void k_fused(const float* adj, const int* idxs,
             const float* lng, const float* lnb,
             const float* sg, const float* sb,
             const float* an_b1, const float* an_w2, const float* an_b2,
             const float* wn_w1, const float* wn_b1,
             const float* alpha_raw,
             const float* Wlin, const float* blin,
             const float* proto_root, const float* proto_neigh,
             const float* proto_rad, const float* proto_dn)
{
  __shared__ __align__(16) char sBuf[26160];
  int tid = threadIdx.x;

  if (blockIdx.x < PROTO_BLOCKS){
    // ================= proto branch: two protos per block =================
    int h = tid >> 7, tl = tid & 127;
    int k = blockIdx.x*2 + h;

    float (*sXT)[FIN][12]  = (float(*)[FIN][12])(sBuf);            // 12288
    float (*sH)[MM][FIN]   = (float(*)[MM][FIN])(sBuf + 12288);    // 10240
    float (*sPp)[NNB][LL]  = (float(*)[NNB][LL])(sBuf + 22528);    // 2304
    float (*sC)[NNB][NNB]  = (float(*)[NNB][NNB])(sBuf + 24832);   // 648
    float (*sCS)[NNB][NNB] = (float(*)[NNB][NNB])(sBuf + 25480);   // 648
    float (*sRed)[4]       = (float(*)[4])(sBuf + 26128);          // 32

    sXT[h][tl][0] = proto_root[k*FIN + tl];
    for (int m=0;m<NNB;m++) sXT[h][tl][m+1] = proto_neigh[(k*NNB+m)*FIN + tl];
    __syncthreads();

    float acc[MM];
    {
      float bias = blin[tl];
      #pragma unroll
      for (int r=0;r<MM;r++) acc[r]=bias;
      for (int i=0;i<FIN;i++){
        float wv = Wlin[i*DXX+tl];
        float4 xa = *(const float4*)&sXT[h][i][0];
        float4 xb = *(const float4*)&sXT[h][i][4];
        float2 xc = *(const float2*)&sXT[h][i][8];
        acc[0]+=xa.x*wv; acc[1]+=xa.y*wv; acc[2]+=xa.z*wv; acc[3]+=xa.w*wv;
        acc[4]+=xb.x*wv; acc[5]+=xb.y*wv; acc[6]+=xb.z*wv; acc[7]+=xb.w*wv;
        acc[8]+=xc.x*wv; acc[9]+=xc.y*wv;
      }
    }
    #pragma unroll
    for (int r=0;r<MM;r++) sH[h][r][tl]=acc[r];
    __syncthreads();
    ln_rows(sH[h], MM, lng, lnb, tl);
    __syncthreads();

    g_hproto_root[k*DXX+tl] = sH[h][0][tl];
    {
      float v = sH[h][0][tl]; v*=v;
      v = wredsum(v);
      if ((tl&31)==0) sRed[h][tl>>5]=v;
    }
    __syncthreads();
    if (tl==0) g_hproto_sq[k] = sRed[h][0]+sRed[h][1]+sRed[h][2]+sRed[h][3];
    if (tl<32){
      float v=0.f;
      for (int d=0;d<DXX;d++) v += sH[h][0][d]*wn_w1[(DXX+d)*32 + tl];
      g_hp[k*32+tl]=v;
    }
    for (int q=tl;q<NNB*LL;q+=128){
      int m=q/LL, l=q%LL;
      float v=0.f;
      for (int d=0;d<DXX;d++) v += sH[h][1+m][d]*g_tnxT[d*LL+l];
      sPp[h][m][l]=v;
    }
    __syncthreads();
    if (tl<LL){
      float vals[NNB];
      for (int m=0;m<NNB;m++) vals[m]=sPp[h][m][tl];
      sort9(vals);
      for (int j=0;j<NNB;j++){
        float v=vals[j];
        g_Pfeat[k*576 + j*LL + tl]       = v;
        g_Pfeat[k*576 + 288 + j*LL + tl] = v*v;
      }
    }
    if (tl < 36){
      int p=tl, i=0;
      while (p >= NNB-1-i){ p -= NNB-1-i; i++; }
      int j = i+1+p;
      float x = proto_dn[tl*KK + k];
      float s = 1.0f/(1.0f+expf(-x));
      sC[h][i][j]=s; sC[h][j][i]=s;
    }
    if (tl < NNB) sC[h][tl][tl]=0.f;
    __syncthreads();
    if (tl < NNB){
      float c[NNB];
      for (int i=0;i<NNB;i++) c[i]=sC[h][i][tl];
      sort9(c);
      for (int i=0;i<NNB;i++) sCS[h][i][tl]=c[i];
    }
    __syncthreads();
    if (tl < NNB){
      float mu=0.f; for(int j=0;j<NNB;j++) mu+=sCS[h][tl][j]; mu*=(1.f/NNB);
      float var=0.f; for(int j=0;j<NNB;j++){float d=sCS[h][tl][j]-mu; var+=d*d;} var*=(1.f/NNB);
      float rstd = rsqrtf(var+1e-5f);
      for (int j=0;j<NNB;j++) sCS[h][tl][j] = (sCS[h][tl][j]-mu)*rstd*sg[j]+sb[j];
    }
    __syncthreads();
    if (tl<LL){
      float vals[NNB];
      for (int m=0;m<NNB;m++){
        float v=0.f;
        for (int j=0;j<NNB;j++) v += sCS[h][m][j]*g_tnsT[j*LL+tl];
        vals[m]=v;
      }
      sort9(vals);
      for (int j=0;j<NNB;j++){
        float v=vals[j];
        g_Pstr[k*576 + j*LL + tl]       = v;
        g_Pstr[k*576 + 288 + j*LL + tl] = v*v;
      }
    }
    if (tl==0){
      float r[NNB];
      for (int j=0;j<NNB;j++) r[j]=proto_rad[k*NNB+j];
      sort9(r);
      for (int j=0;j<NNB;j++){ g_Prad[k*18+j]=r[j]; g_Prad[k*18+9+j]=r[j]*r[j]; }
    }
    return;
  }

  // ================= phase1b branch: warp-per-b =================
  int w = tid >> 5, lane = tid & 31;
  int b = (blockIdx.x - PROTO_BLOCKS)*8 + w;

  float (*sDm)[MM][MM]   = (float(*)[MM][MM])(sBuf);               // 3200
  float (*sHS)[NNB][NNB] = (float(*)[NNB][NNB])(sBuf + 3200);      // 2592
  float (*sHn)[FIN]      = (float(*)[FIN])(sBuf + 5792);           // 4096
  float (*sVm)[NNB]      = (float(*)[NNB])(sBuf + 9888);           // 288
  unsigned (*sNbr)[MM]   = (unsigned(*)[MM])(sBuf + 10176);        // 320
  float (*sTnsT)[32]     = (float(*)[32])(sBuf + 10496);           // 1152

  for (int u=tid; u<NNB*32; u+=256) sTnsT[u>>5][u&31] = g_tnsT[u];

  const float* HR = g_Hraw + (size_t)b*MM*GN;

  if (lane < MM){
    int idv = idxs[b*MM + lane];
    if (lane >= 1) sVm[w][lane-1] = (idv != NALL) ? 1.f : 0.f;
    unsigned nb=0;
    const float* arow = adj + (size_t)b*MM*MM + lane*MM;
    #pragma unroll
    for (int j=0;j<MM;j++) if (arow[j] > 1e-5f) nb |= (1u<<j);
    sNbr[w][lane]=nb;
  }
  __syncthreads();

  float vs = 0.f;
  #pragma unroll
  for (int j=0;j<NNB;j++) vs += sVm[w][j];
  float vsi = 1.f/(vs + 1e-9f);

  if (lane < MM){
    float drow[MM];
    #pragma unroll
    for (int j=0;j<MM;j++) drow[j] = (j==lane)?0.f:10.f;
    unsigned reach = 1u<<lane, frontier = 1u<<lane;
    for (int step=1; step<MM; step++){
      unsigned nxt=0;
      #pragma unroll
      for (int v=0;v<MM;v++) if (frontier & (1u<<v)) nxt |= sNbr[w][v];
      nxt &= ~reach;
      if (!nxt) break;
      #pragma unroll
      for (int v=0;v<MM;v++) if (nxt & (1u<<v)) drow[v]=(float)step;
      reach |= nxt; frontier = nxt;
    }
    #pragma unroll
    for (int j=0;j<MM;j++) sDm[w][lane][j]=drow[j];
  }
  __syncwarp();
  for (int q=lane; q<MM*MM; q+=32){
    int i=q/MM, j=q%MM;
    float fi = (i==0)?1.f:sVm[w][i-1];
    float fj = (j==0)?1.f:sVm[w][j-1];
    sDm[w][i][j] = (fi*fj>0.f) ? sDm[w][i][j]*0.1f : 1.0f;
  }
  __syncwarp();

  // ---- batched LN statistics: one butterfly pass for all 10 rows (sum + sumsq) ----
  float sv[MM], qv[MM];
  float a00, a01, a02, a03;
  #pragma unroll
  for (int r=0;r<MM;r++){
    const float* Hr = HR + r*GN;
    float a0=Hr[lane], a1=Hr[lane+32], a2=Hr[lane+64], a3=Hr[lane+96];
    sv[r] = (a0+a1)+(a2+a3);
    qv[r] = (a0*a0+a1*a1)+(a2*a2+a3*a3);
    if (r==0){ a00=a0; a01=a1; a02=a2; a03=a3; }
  }
  #pragma unroll
  for (int o=16;o;o>>=1){
    #pragma unroll
    for (int r=0;r<MM;r++){
      sv[r] += __shfl_xor_sync(0xffffffffu, sv[r], o);
      qv[r] += __shfl_xor_sync(0xffffffffu, qv[r], o);
    }
  }
  float muv[NNB], rsv[NNB];
  float mu0 = sv[0]*(1.f/FIN);
  float rs0 = rsqrtf(fmaxf(qv[0]*(1.f/FIN) - mu0*mu0, 0.f) + 1e-5f);
  #pragma unroll
  for (int r=1;r<MM;r++){
    float mu = sv[r]*(1.f/FIN);
    muv[r-1] = mu;
    rsv[r-1] = rsqrtf(fmaxf(qv[r]*(1.f/FIN) - mu*mu, 0.f) + 1e-5f);
  }
  // row 0 -> hn / hroot / hrsq
  {
    float lg0=lng[lane], lg1=lng[lane+32], lg2=lng[lane+64], lg3=lng[lane+96];
    float lb0=lnb[lane], lb1=lnb[lane+32], lb2=lnb[lane+64], lb3=lnb[lane+96];
    float h0=(a00-mu0)*rs0*lg0+lb0, h1=(a01-mu0)*rs0*lg1+lb1;
    float h2=(a02-mu0)*rs0*lg2+lb2, h3=(a03-mu0)*rs0*lg3+lb3;
    sHn[w][lane]=h0; sHn[w][lane+32]=h1; sHn[w][lane+64]=h2; sHn[w][lane+96]=h3;
    g_hroot[(size_t)b*DXX+lane]=h0; g_hroot[(size_t)b*DXX+lane+32]=h1;
    g_hroot[(size_t)b*DXX+lane+64]=h2; g_hroot[(size_t)b*DXX+lane+96]=h3;
    float qq = wredsum((h0*h0+h1*h1)+(h2*h2+h3*h3));
    if (lane==0) g_hrootsq[b]=qq;
  }
  __syncwarp();

  if (lane < NNB){
    float c[NNB];
    #pragma unroll
    for (int i=0;i<NNB;i++) c[i]=sDm[w][1+i][1+lane];
    sort9(c);
    #pragma unroll
    for (int i=0;i<NNB;i++) sHS[w][i][lane]=c[i];
  }
  __syncwarp();
  if (lane < NNB){
    float mu=0.f;
    #pragma unroll
    for (int j=0;j<NNB;j++) mu+=sHS[w][lane][j];
    mu *= (1.f/NNB);
    float var=0.f;
    #pragma unroll
    for (int j=0;j<NNB;j++){ float d=sHS[w][lane][j]-mu; var+=d*d; }
    var *= (1.f/NNB);
    float rstd=rsqrtf(var+1e-5f);
    #pragma unroll
    for (int j=0;j<NNB;j++) sHS[w][lane][j]=(sHS[w][lane][j]-mu)*rstd*sg[j]+sb[j];
  }
  __syncwarp();

  {
    float cSgl=g_cSg[lane], cCbl=g_cCb[lane];
    float vals[NNB]; int ord[NNB];
    #pragma unroll
    for (int m=0;m<NNB;m++)
      vals[m] = rsv[m]*(HR[(1+m)*GN+128+lane] - muv[m]*cSgl) + cCbl;
    argsort9(vals, ord);
    float t1=0.f;
    #pragma unroll
    for (int j=0;j<NNB;j++){
      int mo=ord[j];
      float wv = sVm[w][mo]*vsi;
      float pv = vals[mo];
      g_Afeat[(size_t)b*576 + j*LL + lane]       = -2.f*wv*pv;
      g_Afeat[(size_t)b*576 + 288 + j*LL + lane] = wv;
      t1 += wv*pv*pv;
    }
    t1 = wredsum(t1);
    if (lane==0) g_T1feat[b]=t1;
  }
  {
    float vals[NNB]; int ord[NNB];
    #pragma unroll
    for (int m=0;m<NNB;m++){
      float v2=0.f;
      #pragma unroll
      for (int j=0;j<NNB;j++) v2 += sHS[w][m][j]*sTnsT[j][lane];
      vals[m]=v2;
    }
    argsort9(vals, ord);
    float t1=0.f;
    #pragma unroll
    for (int j=0;j<NNB;j++){
      int mo=ord[j];
      float wv = sVm[w][mo]*vsi;
      float pv = vals[mo];
      g_Astr[(size_t)b*576 + j*LL + lane]       = -2.f*wv*pv;
      g_Astr[(size_t)b*576 + 288 + j*LL + lane] = wv;
      t1 += wv*pv*pv;
    }
    t1 = wredsum(t1);
    if (lane==0) g_T1str[b]=t1;
  }
  if (lane==0){
    float rb[NNB]; int ord[NNB];
    #pragma unroll
    for (int j=0;j<NNB;j++) rb[j]=sDm[w][0][1+j];
    argsort9(rb, ord);
    float S=0.f;
    #pragma unroll
    for (int j=0;j<NNB;j++){
      int mo=ord[j];
      float wv=sVm[w][mo]*vsi;
      float v=rb[mo];
      g_Arad[(size_t)b*18+j]   = -2.f*wv*v;
      g_Arad[(size_t)b*18+9+j] = wv;
      S += wv*v*v;
    }
    g_Srad[b]=S;
  }
  {
    float v0 = wn_b1[lane], v1=0.f, v2=0.f, v3=0.f;
    #pragma unroll 8
    for (int d=0; d<DXX; d+=4){
      v0 += sHn[w][d+0]*wn_w1[(d+0)*32+lane];
      v1 += sHn[w][d+1]*wn_w1[(d+1)*32+lane];
      v2 += sHn[w][d+2]*wn_w1[(d+2)*32+lane];
      v3 += sHn[w][d+3]*wn_w1[(d+3)*32+lane];
    }
    g_hb[(size_t)b*32+lane] = (v0+v1)+(v2+v3);
  }
  {
    float cSga=g_cSg[32+lane], cCba=g_cCb[32+lane];
    float s=0.f;
    #pragma unroll
    for (int m=0;m<NNB;m++){
      float av = rsv[m]*(HR[(1+m)*GN+160+lane] - muv[m]*cSga) + cCba;
      s += sVm[w][m]*av;
    }
    float hid = fmaxf(an_b1[lane] + s*vsi, 0.f);
    float vv = wredsum(hid*an_w2[lane]);
    if (lane==0)
      g_alpha[b] = 1.0f/(1.0f+expf(-(alpha_raw[0] + vv + an_b2[0])));
  }
}

// ------------------- kernel 3: register-tiled combine -------------------
__device__ __forceinline__ void p2_loadA(const float* Aptr, int b0, int c0,
                                         int strideA, float scale,
                                         float (*sA)[20], int tid){
  #pragma unroll
  for (int it=0; it<2; it++){
    int u = tid + it*128;
    int bb = u >> 4, cq = u & 15;
    float4 v = *(const float4*)&Aptr[(size_t)(b0+bb)*strideA + c0 + cq*4];
    int c = cq*4;
    sA[c+0][bb]=v.x*scale; sA[c+1][bb]=v.y*scale;
    sA[c+2][bb]=v.z*scale; sA[c+3][bb]=v.w*scale;
  }
}
__device__ __forceinline__ void p2_loadP(const float* Pptr, int c0,
                                         int strideP, float (*sP)[68], int tid){
  #pragma unroll
  for (int it=0; it<8; it++){
    int u = tid + it*128;
    int kk = u >> 4, cq = u & 15;
    float4 v = *(const float4*)&Pptr[(size_t)kk*strideP + c0 + cq*4];
    int c = cq*4;
    sP[c+0][kk]=v.x; sP[c+1][kk]=v.y; sP[c+2][kk]=v.z; sP[c+3][kk]=v.w;
  }
}
__device__ __forceinline__ void p2_compute(const float (*sA)[20], const float (*sP)[68],
                                           int bg, int kg, float* acc){
  #pragma unroll 8
  for (int c=0;c<64;c++){
    float2 a = *(const float2*)&sA[c][bg*2];
    float4 p = *(const float4*)&sP[c][kg*4];
    acc[0]+=a.x*p.x; acc[1]+=a.x*p.y; acc[2]+=a.x*p.z; acc[3]+=a.x*p.w;
    acc[4]+=a.y*p.x; acc[5]+=a.y*p.y; acc[6]+=a.y*p.z; acc[7]+=a.y*p.w;
  }
}

__global__ __launch_bounds__(128)
void k_phase2(const float* wn_w2, const float* wn_b2, const float* w_raw,
              const float* log_gamma, float* out)
{
  int tid = threadIdx.x;
  int bg = tid >> 4;
  int kg = tid & 15;
  int b0 = blockIdx.x * TB2;

  __shared__ __align__(16) float sA[64][20];
  __shared__ __align__(16) float sP[64][68];
  __shared__ float sHb[TB2][33];
  __shared__ float sHp[KK][33];
  __shared__ float sArad[TB2][19];
  __shared__ float sPrad[KK][19];
  __shared__ float sScB[TB2][5];
  __shared__ float sHpsq[KK];
  __shared__ float sW2[32];

  for (int idx=tid; idx<TB2*32; idx+=128){ int bb=idx>>5, j=idx&31; sHb[bb][j]=g_hb[(size_t)(b0+bb)*32+j]; }
  for (int idx=tid; idx<KK*32; idx+=128){ int kk=idx>>5, j=idx&31; sHp[kk][j]=g_hp[kk*32+j]; }
  for (int idx=tid; idx<TB2*18; idx+=128){ int bb=idx/18, j=idx%18; sArad[bb][j]=g_Arad[(size_t)(b0+bb)*18+j]; }
  for (int idx=tid; idx<KK*18; idx+=128){ int kk=idx/18, j=idx%18; sPrad[kk][j]=g_Prad[kk*18+j]; }
  for (int idx=tid; idx<TB2*5; idx+=128){
    int bb=idx/5, q=idx%5, bgl=b0+bb;
    float v;
    switch(q){
      case 0: v=g_T1feat[bgl]; break;
      case 1: v=g_T1str[bgl];  break;
      case 2: v=g_Srad[bgl];   break;
      case 3: v=g_hrootsq[bgl];break;
      default:v=g_alpha[bgl];
    }
    sScB[bb][q]=v;
  }
  if (tid < KK) sHpsq[tid]=g_hproto_sq[tid];
  if (tid < 32) sW2[tid]=wn_w2[tid];

  float accF[8], accS[8], accR[8];
  #pragma unroll
  for (int q=0;q<8;q++){ accF[q]=0.f; accS[q]=0.f; accR[q]=0.f; }

  for (int ch=0; ch<9; ch++){
    __syncthreads();
    p2_loadA(g_Afeat, b0, ch*64, 576, 1.f, sA, tid);
    p2_loadP(g_Pfeat, ch*64, 576, sP, tid);
    __syncthreads();
    p2_compute(sA, sP, bg, kg, accF);
  }
  for (int ch=0; ch<9; ch++){
    __syncthreads();
    p2_loadA(g_Astr, b0, ch*64, 576, 1.f, sA, tid);
    p2_loadP(g_Pstr, ch*64, 576, sP, tid);
    __syncthreads();
    p2_compute(sA, sP, bg, kg, accS);
  }
  for (int ch=0; ch<2; ch++){
    __syncthreads();
    p2_loadA(g_hroot, b0, ch*64, DXX, -2.f, sA, tid);
    p2_loadP(g_hproto_root, ch*64, DXX, sP, tid);
    __syncthreads();
    p2_compute(sA, sP, bg, kg, accR);
  }

  float accD[8];
  #pragma unroll
  for (int q=0;q<8;q++) accD[q]=0.f;
  #pragma unroll
  for (int j=0;j<18;j++){
    float a0=sArad[bg*2+0][j], a1=sArad[bg*2+1][j];
    float p0=sPrad[kg*4+0][j], p1=sPrad[kg*4+1][j], p2=sPrad[kg*4+2][j], p3=sPrad[kg*4+3][j];
    accD[0]+=a0*p0; accD[1]+=a0*p1; accD[2]+=a0*p2; accD[3]+=a0*p3;
    accD[4]+=a1*p0; accD[5]+=a1*p1; accD[6]+=a1*p2; accD[7]+=a1*p3;
  }

  float wlog[8];
  #pragma unroll
  for (int q=0;q<8;q++) wlog[q]=0.f;
  #pragma unroll 8
  for (int j=0;j<32;j++){
    float w2 = sW2[j];
    float b0v=sHb[bg*2+0][j], b1v=sHb[bg*2+1][j];
    float p0=sHp[kg*4+0][j], p1=sHp[kg*4+1][j], p2=sHp[kg*4+2][j], p3=sHp[kg*4+3][j];
    wlog[0]+=fmaxf(b0v+p0,0.f)*w2; wlog[1]+=fmaxf(b0v+p1,0.f)*w2;
    wlog[2]+=fmaxf(b0v+p2,0.f)*w2; wlog[3]+=fmaxf(b0v+p3,0.f)*w2;
    wlog[4]+=fmaxf(b1v+p0,0.f)*w2; wlog[5]+=fmaxf(b1v+p1,0.f)*w2;
    wlog[6]+=fmaxf(b1v+p2,0.f)*w2; wlog[7]+=fmaxf(b1v+p3,0.f)*w2;
  }

  float wraw = w_raw[0], wb2 = wn_b2[0];
  float gamma = expf(log_gamma[0]);

  #pragma unroll
  for (int i=0;i<2;i++){
    int bi = bg*2+i;
    float T1f=sScB[bi][0], T1s=sScB[bi][1], Sr=sScB[bi][2], hrsq=sScB[bi][3], al=sScB[bi][4];
    float res[4];
    #pragma unroll
    for (int j=0;j<4;j++){
      int q = i*4+j;
      int kk = kg*4+j;
      float wgt = 1.f/(1.f+expf(-(wraw + wlog[q] + wb2)));
      float drf = hrsq + sHpsq[kk] + accR[q];
      float swf = (T1f + accF[q])*(1.f/(float)LL);
      float sws = (T1s + accS[q])*(1.f/(float)LL);
      float rad = Sr + accD[q];
      float df = wgt*drf + (1.f-wgt)*swf;
      float ds = wgt*rad + (1.f-wgt)*sws;
      float dfgw = al*df + (1.f-al)*ds;
      res[j] = expf(-gamma*dfgw);
    }
    *(float4*)&out[(size_t)(b0+bi)*KK + kg*4] = make_float4(res[0],res[1],res[2],res[3]);
  }
}

// ------------------- launcher -------------------
extern "C" void kernel_launch(void* const* d_in, const int* in_sizes, int n_in,
                              void* d_out, int out_size)
{
  const float* adj        = (const float*)d_in[0];
  const float* features   = (const float*)d_in[1];
  const int*   idxs       = (const int*)  d_in[2];
  const float* x_lin_w    = (const float*)d_in[3];
  const float* x_lin_b    = (const float*)d_in[4];
  const float* x_ln_g     = (const float*)d_in[5];
  const float* x_ln_b     = (const float*)d_in[6];
  const float* s_ln_g     = (const float*)d_in[7];
  const float* s_ln_b     = (const float*)d_in[8];
  const float* theta_x    = (const float*)d_in[9];
  const float* theta_s    = (const float*)d_in[10];
  const float* alpha_raw  = (const float*)d_in[11];
  const float* an_w1      = (const float*)d_in[12];
  const float* an_b1      = (const float*)d_in[13];
  const float* an_w2      = (const float*)d_in[14];
  const float* an_b2      = (const float*)d_in[15];
  const float* wn_w1      = (const float*)d_in[16];
  const float* wn_b1      = (const float*)d_in[17];
  const float* wn_w2      = (const float*)d_in[18];
  const float* wn_b2      = (const float*)d_in[19];
  const float* w_raw      = (const float*)d_in[20];
  const float* proto_root = (const float*)d_in[21];
  const float* proto_neigh= (const float*)d_in[22];
  const float* proto_rad  = (const float*)d_in[23];
  const float* proto_dn   = (const float*)d_in[24];
  const float* log_gamma  = (const float*)d_in[25];
  float* out = (float*)d_out;

  cudaFuncSetAttribute(k_lin_mma, cudaFuncAttributeMaxDynamicSharedMemorySize, SMEM_LIN);

  k_tn<<<1,128>>>(theta_x, theta_s);
  k_prep<<<41,256>>>(x_lin_w, x_lin_b, x_ln_g, x_ln_b, an_w1);
  k_prepB<<<192,256>>>();
  k_lin_mma<<<(BB*MM)/128, 512, SMEM_LIN>>>(features, idxs);
  k_fused<<<PROTO_BLOCKS + BB/8, 256>>>(adj, idxs, x_ln_g, x_ln_b, s_ln_g, s_ln_b,
                                        an_b1, an_w2, an_b2, wn_w1, wn_b1, alpha_raw,
                                        x_lin_w, x_lin_b, proto_root, proto_neigh,
                                        proto_rad, proto_dn);
  k_phase2<<<BB/TB2,128>>>(wn_w2, wn_b2, w_raw, log_gamma, out);
}

// round 12
// speedup vs baseline: 1.5365x; 1.0063x over previous
#include <cuda_runtime.h>
#include <cuda_bf16.h>
#include <math.h>
#include <stdint.h>

#define BB   8192
#define MM   10
#define NNB  9
#define FIN  128
#define DXX  128
#define KK   64
#define LL   32
#define NALL 100000
#define GN   192
#define TB2  16

// ------------------- device scratch -------------------
__device__ float g_tnxT[FIN*LL];
__device__ float g_tnsT[NNB*LL];
__device__ float g_biasv[GN];
__device__ float g_cSg[64];
__device__ float g_cCb[64];
__device__ float g_Hraw[(size_t)BB*MM*GN];
__device__ __align__(16) __nv_bfloat16 g_BtileH[2*GN*136];   // [half][n][k_pad136]

__device__ float g_hproto_root[KK*DXX];
__device__ float g_hproto_sq[KK];
__device__ float g_hp[KK*32];
__device__ float g_Pfeat[KK*576];
__device__ float g_Pstr[KK*576];
__device__ float g_Prad[KK*18];

__device__ float g_hroot[BB*DXX];
__device__ float g_hrootsq[BB];
__device__ float g_hb[BB*32];
__device__ float g_alpha[BB];
__device__ float g_Afeat[(size_t)BB*576];
__device__ float g_T1feat[BB];
__device__ float g_Astr[(size_t)BB*576];
__device__ float g_T1str[BB];
__device__ float g_Arad[BB*18];
__device__ float g_Srad[BB];

// ------------------- helpers -------------------
__device__ __forceinline__ void sort9(float* v){
  for (int a=1;a<NNB;a++){
    float x=v[a]; int c=a-1;
    while (c>=0 && v[c]>x){ v[c+1]=v[c]; c--; }
    v[c+1]=x;
  }
}
__device__ __forceinline__ void argsort9(const float* v, int* ord){
  for (int a=0;a<NNB;a++) ord[a]=a;
  for (int a=1;a<NNB;a++){
    int o=ord[a]; float x=v[o]; int c=a-1;
    while (c>=0 && v[ord[c]]>x){ ord[c+1]=ord[c]; c--; }
    ord[c+1]=o;
  }
}
__device__ __forceinline__ float wredsum(float v){
  #pragma unroll
  for (int o=16;o;o>>=1) v += __shfl_xor_sync(0xffffffffu, v, o);
  return v;
}
__device__ __forceinline__ void ln_rows(float (*sH)[FIN], int nrows,
                                        const float* g, const float* b, int t){
  int w = t>>5, lane = t&31;
  for (int r=w; r<nrows; r+=4){
    float s=0.f;
    for (int j=lane;j<FIN;j+=32) s += sH[r][j];
    s = wredsum(s);
    float mu = s*(1.f/FIN);
    float s2=0.f;
    for (int j=lane;j<FIN;j+=32){ float d=sH[r][j]-mu; s2 += d*d; }
    s2 = wredsum(s2);
    float rstd = rsqrtf(s2*(1.f/FIN)+1e-5f);
    for (int j=lane;j<FIN;j+=32) sH[r][j] = (sH[r][j]-mu)*rstd*g[j] + b[j];
  }
}
__device__ __forceinline__ uint32_t smem_u32(const void* p){
  uint32_t a;
  asm("{ .reg .u64 t; cvta.to.shared.u64 t, %1; cvt.u32.u64 %0, t; }" : "=r"(a) : "l"(p));
  return a;
}
// ---- sm_80-compatible tensor core ops ----
__device__ __forceinline__ void ldsm_x4(uint32_t* r, uint32_t addr){
  asm volatile("ldmatrix.sync.aligned.m8n8.x4.shared.b16 {%0,%1,%2,%3}, [%4];"
    : "=r"(r[0]),"=r"(r[1]),"=r"(r[2]),"=r"(r[3]) : "r"(addr));
}
__device__ __forceinline__ void ldsm_x2(uint32_t* r, uint32_t addr){
  asm volatile("ldmatrix.sync.aligned.m8n8.x2.shared.b16 {%0,%1}, [%2];"
    : "=r"(r[0]),"=r"(r[1]) : "r"(addr));
}
__device__ __forceinline__ void mma16816(float* c, const uint32_t* a, const uint32_t* b){
  asm volatile(
    "mma.sync.aligned.m16n8k16.row.col.f32.bf16.bf16.f32 "
    "{%0,%1,%2,%3}, {%4,%5,%6,%7}, {%8,%9}, {%0,%1,%2,%3};"
    : "+f"(c[0]),"+f"(c[1]),"+f"(c[2]),"+f"(c[3])
    : "r"(a[0]),"r"(a[1]),"r"(a[2]),"r"(a[3]), "r"(b[0]),"r"(b[1]));
}

// ------------------- kernel 0: normalize thetas -------------------
__global__ void k_tn(const float* theta_x, const float* theta_s){
  int t = threadIdx.x, w=t>>5, lane=t&31;
  for (int row=w; row<LL; row+=4){
    float s=0.f;
    for (int j=lane;j<FIN;j+=32){ float v=theta_x[row*FIN+j]; s+=v*v; }
    s = wredsum(s);
    float inv = 1.0f/sqrtf(s);
    for (int j=lane;j<FIN;j+=32) g_tnxT[j*LL+row] = theta_x[row*FIN+j]*inv;
  }
  if (t < LL){
    float s=0.f;
    for (int j=0;j<NNB;j++){ float v=theta_s[t*NNB+j]; s+=v*v; }
    float inv = 1.0f/sqrtf(s);
    for (int j=0;j<NNB;j++) g_tnsT[j*LL+t] = theta_s[t*NNB+j]*inv;
  }
}

// ------------------- kernel 0b: folded B -> bf16 hi/lo tiles directly -------------------
__global__ void k_prep(const float* Wlin, const float* blin,
                       const float* lng, const float* lnb,
                       const float* an_w1){
  int bid = blockIdx.x, t = threadIdx.x;
  if (bid < 32){
    // fold cols: n = 128 + c, k = i
    int out = bid*256 + t;
    int i = out >> 6, c = out & 63;
    float acc = 0.f;
    for (int d=0; d<FIN; d++){
      float th = (c<32) ? g_tnxT[d*LL + c] : an_w1[d*32 + (c-32)];
      acc += Wlin[i*DXX + d] * (lng[d]*th);
    }
    __nv_bfloat16 hb = __float2bfloat16(acc);
    __nv_bfloat16 lb = __float2bfloat16(acc - __bfloat162float(hb));
    int n = 128 + c;
    g_BtileH[(0*GN + n)*136 + i] = hb;
    g_BtileH[(1*GN + n)*136 + i] = lb;
  } else if (bid < 40){
    // W copy: n = u&127, k = u>>7
    int base = (bid-32)*2048;
    for (int it=0; it<8; it++){
      int u = base + t + it*256;
      float v = Wlin[u];
      int k = u >> 7, n = u & 127;
      __nv_bfloat16 hb = __float2bfloat16(v);
      __nv_bfloat16 lb = __float2bfloat16(v - __bfloat162float(hb));
      g_BtileH[(0*GN + n)*136 + k] = hb;
      g_BtileH[(1*GN + n)*136 + k] = lb;
    }
  } else {
    if (t < 128) g_biasv[t] = blin[t];
    if (t < 64){
      float bs=0.f, sg=0.f, cb=0.f;
      for (int d=0; d<FIN; d++){
        float th = (t<32) ? g_tnxT[d*LL + t] : an_w1[d*32 + (t-32)];
        float v = lng[d]*th;
        bs += blin[d]*v;
        sg += v;
        cb += lnb[d]*th;
      }
      g_biasv[128+t]=bs; g_cSg[t]=sg; g_cCb[t]=cb;
    }
  }
}

// ------------------- kernel 2a: split-bf16 mma.sync gathered GEMM (512 thr, 16 warps) ----
#define SM_IDX   0
#define SM_BIAS  512
#define SM_AHI   2048
#define SM_ALO   (SM_AHI + 128*136*2)
#define SM_BHI   (SM_ALO + 128*136*2)
#define SM_BLO   (SM_BHI + 192*136*2)
#define SMEM_LIN (SM_BLO + 192*136*2)      // 176128 bytes
#define STG_STRIDE 196

__global__ __launch_bounds__(512)
void k_lin_mma(const float* features, const int* idxs)
{
  extern __shared__ char smem[];
  int tid = threadIdx.x;
  int wid = tid >> 5, lane = tid & 31;
  size_t row0 = (size_t)blockIdx.x * 128;
  int* sIdx = (int*)(smem + SM_IDX);
  float* sBias = (float*)(smem + SM_BIAS);

  if (tid < 128) sIdx[tid] = idxs[row0 + tid];
  if (tid >= 256 && tid < 448) sBias[tid-256] = g_biasv[tid-256];

  {
    const uint4* src = (const uint4*)g_BtileH;
    uint4* dst = (uint4*)(smem + SM_BHI);
    #pragma unroll
    for (int i=0;i<13;i++){
      int u = tid + i*512;
      if (u < 6528) dst[u] = src[u];
    }
  }
  __syncthreads();

  #pragma unroll
  for (int i=0;i<8;i++){
    int u = tid + i*512;
    int row = u >> 5, q = u & 31;
    int id = sIdx[row];
    float4 v;
    if (id == NALL) v = make_float4(0.f,0.f,0.f,0.f);
    else v = *(const float4*)&features[(size_t)id*FIN + q*4];
    __nv_bfloat162 h01 = __floats2bfloat162_rn(v.x, v.y);
    __nv_bfloat162 h23 = __floats2bfloat162_rn(v.z, v.w);
    float2 f01 = __bfloat1622float2(h01);
    float2 f23 = __bfloat1622float2(h23);
    __nv_bfloat162 l01 = __floats2bfloat162_rn(v.x - f01.x, v.y - f01.y);
    __nv_bfloat162 l23 = __floats2bfloat162_rn(v.z - f23.x, v.w - f23.y);
    uint32_t off = (uint32_t)(row*136 + q*4)*2;
    *(__nv_bfloat162*)(smem + SM_AHI + off)     = h01;
    *(__nv_bfloat162*)(smem + SM_AHI + off + 4) = h23;
    *(__nv_bfloat162*)(smem + SM_ALO + off)     = l01;
    *(__nv_bfloat162*)(smem + SM_ALO + off + 4) = l23;
  }
  __syncthreads();

  int wm = wid >> 1, wn = wid & 1;
  int mbase = wm*16, nbase = wn*96;
  uint32_t sb = smem_u32(smem);

  float acc[12][4];
  #pragma unroll
  for (int j=0;j<12;j++)
    #pragma unroll
    for (int q=0;q<4;q++) acc[j][q]=0.f;

  int aRow = mbase + ((lane>>3)&1)*8 + (lane&7);
  int aK   = (lane>>4)*8;
  int bRow = nbase + (lane&7);
  int bK   = ((lane>>3)&1)*8;

  #pragma unroll
  for (int kc=0; kc<8; kc++){
    uint32_t bf[12][2];
    #pragma unroll
    for (int j=0;j<12;j++)
      ldsm_x2(bf[j], sb + SM_BHI + (uint32_t)((bRow + j*8)*136 + kc*16 + bK)*2);
    uint32_t af[4];
    ldsm_x4(af, sb + SM_AHI + (uint32_t)(aRow*136 + kc*16 + aK)*2);
    #pragma unroll
    for (int j=0;j<12;j++) mma16816(acc[j], af, bf[j]);
    ldsm_x4(af, sb + SM_ALO + (uint32_t)(aRow*136 + kc*16 + aK)*2);
    #pragma unroll
    for (int j=0;j<12;j++) mma16816(acc[j], af, bf[j]);
  }
  #pragma unroll
  for (int kc=0; kc<8; kc++){
    uint32_t bf[12][2];
    #pragma unroll
    for (int j=0;j<12;j++)
      ldsm_x2(bf[j], sb + SM_BLO + (uint32_t)((bRow + j*8)*136 + kc*16 + bK)*2);
    uint32_t af[4];
    ldsm_x4(af, sb + SM_AHI + (uint32_t)(aRow*136 + kc*16 + aK)*2);
    #pragma unroll
    for (int j=0;j<12;j++) mma16816(acc[j], af, bf[j]);
  }
  __syncthreads();

  float* stage = (float*)(smem + SM_AHI);
  {
    int r = lane >> 2, c2 = 2*(lane & 3);
    int rr = mbase + r;
    #pragma unroll
    for (int j=0;j<12;j++){
      int cc = nbase + j*8 + c2;
      float b0 = sBias[cc], b1 = sBias[cc+1];
      *(float2*)&stage[rr*STG_STRIDE + cc]     = make_float2(acc[j][0]+b0, acc[j][1]+b1);
      *(float2*)&stage[(rr+8)*STG_STRIDE + cc] = make_float2(acc[j][2]+b0, acc[j][3]+b1);
    }
  }
  __syncthreads();
  #pragma unroll
  for (int i=0;i<12;i++){
    int u = tid + i*512;
    int row = u/48, q = u%48;
    *(float4*)&g_Hraw[(row0 + row)*GN + q*4] = *(float4*)&stage[row*STG_STRIDE + q*4];
  }
}

// ------------------- fused kernel: blocks [0,32) proto (2/block);
//                     blocks [32, 32+1024) phase1b warp-per-b ----
#define PROTO_BLOCKS (KK/2)

__global__ __launch_bounds__(256)
void k_fused(const float* adj, const int* idxs,
             const float* lng, const float* lnb,
             const float* sg, const float* sb,
             const float* an_b1, const float* an_w2, const float* an_b2,
             const float* wn_w1, const float* wn_b1,
             const float* alpha_raw,
             const float* Wlin, const float* blin,
             const float* proto_root, const float* proto_neigh,
             const float* proto_rad, const float* proto_dn)
{
  __shared__ __align__(16) char sBuf[28032];
  int tid = threadIdx.x;

  if (blockIdx.x < PROTO_BLOCKS){
    // ================= proto branch: two protos per block =================
    int h = tid >> 7, tl = tid & 127;
    int k = blockIdx.x*2 + h;

    float (*sXT)[FIN][12]  = (float(*)[FIN][12])(sBuf);            // 12288
    float (*sH)[MM][FIN]   = (float(*)[MM][FIN])(sBuf + 12288);    // 10240
    float (*sPp)[NNB][LL]  = (float(*)[NNB][LL])(sBuf + 22528);    // 2304
    float (*sC)[NNB][NNB]  = (float(*)[NNB][NNB])(sBuf + 24832);   // 648
    float (*sCS)[NNB][NNB] = (float(*)[NNB][NNB])(sBuf + 25480);   // 648
    float (*sRed)[4]       = (float(*)[4])(sBuf + 26128);          // 32

    sXT[h][tl][0] = proto_root[k*FIN + tl];
    for (int m=0;m<NNB;m++) sXT[h][tl][m+1] = proto_neigh[(k*NNB+m)*FIN + tl];
    __syncthreads();

    float acc[MM];
    {
      float bias = blin[tl];
      #pragma unroll
      for (int r=0;r<MM;r++) acc[r]=bias;
      for (int i=0;i<FIN;i++){
        float wv = Wlin[i*DXX+tl];
        float4 xa = *(const float4*)&sXT[h][i][0];
        float4 xb = *(const float4*)&sXT[h][i][4];
        float2 xc = *(const float2*)&sXT[h][i][8];
        acc[0]+=xa.x*wv; acc[1]+=xa.y*wv; acc[2]+=xa.z*wv; acc[3]+=xa.w*wv;
        acc[4]+=xb.x*wv; acc[5]+=xb.y*wv; acc[6]+=xb.z*wv; acc[7]+=xb.w*wv;
        acc[8]+=xc.x*wv; acc[9]+=xc.y*wv;
      }
    }
    #pragma unroll
    for (int r=0;r<MM;r++) sH[h][r][tl]=acc[r];
    __syncthreads();
    ln_rows(sH[h], MM, lng, lnb, tl);
    __syncthreads();

    g_hproto_root[k*DXX+tl] = sH[h][0][tl];
    {
      float v = sH[h][0][tl]; v*=v;
      v = wredsum(v);
      if ((tl&31)==0) sRed[h][tl>>5]=v;
    }
    __syncthreads();
    if (tl==0) g_hproto_sq[k] = sRed[h][0]+sRed[h][1]+sRed[h][2]+sRed[h][3];
    if (tl<32){
      float v=0.f;
      for (int d=0;d<DXX;d++) v += sH[h][0][d]*wn_w1[(DXX+d)*32 + tl];
      g_hp[k*32+tl]=v;
    }
    for (int q=tl;q<NNB*LL;q+=128){
      int m=q/LL, l=q%LL;
      float v=0.f;
      for (int d=0;d<DXX;d++) v += sH[h][1+m][d]*g_tnxT[d*LL+l];
      sPp[h][m][l]=v;
    }
    __syncthreads();
    if (tl<LL){
      float vals[NNB];
      for (int m=0;m<NNB;m++) vals[m]=sPp[h][m][tl];
      sort9(vals);
      for (int j=0;j<NNB;j++){
        float v=vals[j];
        g_Pfeat[k*576 + j*LL + tl]       = v;
        g_Pfeat[k*576 + 288 + j*LL + tl] = v*v;
      }
    }
    if (tl < 36){
      int p=tl, i=0;
      while (p >= NNB-1-i){ p -= NNB-1-i; i++; }
      int j = i+1+p;
      float x = proto_dn[tl*KK + k];
      float s = 1.0f/(1.0f+expf(-x));
      sC[h][i][j]=s; sC[h][j][i]=s;
    }
    if (tl < NNB) sC[h][tl][tl]=0.f;
    __syncthreads();
    if (tl < NNB){
      float c[NNB];
      for (int i=0;i<NNB;i++) c[i]=sC[h][i][tl];
      sort9(c);
      for (int i=0;i<NNB;i++) sCS[h][i][tl]=c[i];
    }
    __syncthreads();
    if (tl < NNB){
      float mu=0.f; for(int j=0;j<NNB;j++) mu+=sCS[h][tl][j]; mu*=(1.f/NNB);
      float var=0.f; for(int j=0;j<NNB;j++){float d=sCS[h][tl][j]-mu; var+=d*d;} var*=(1.f/NNB);
      float rstd = rsqrtf(var+1e-5f);
      for (int j=0;j<NNB;j++) sCS[h][tl][j] = (sCS[h][tl][j]-mu)*rstd*sg[j]+sb[j];
    }
    __syncthreads();
    if (tl<LL){
      float vals[NNB];
      for (int m=0;m<NNB;m++){
        float v=0.f;
        for (int j=0;j<NNB;j++) v += sCS[h][m][j]*g_tnsT[j*LL+tl];
        vals[m]=v;
      }
      sort9(vals);
      for (int j=0;j<NNB;j++){
        float v=vals[j];
        g_Pstr[k*576 + j*LL + tl]       = v;
        g_Pstr[k*576 + 288 + j*LL + tl] = v*v;
      }
    }
    if (tl==0){
      float r[NNB];
      for (int j=0;j<NNB;j++) r[j]=proto_rad[k*NNB+j];
      sort9(r);
      for (int j=0;j<NNB;j++){ g_Prad[k*18+j]=r[j]; g_Prad[k*18+9+j]=r[j]*r[j]; }
    }
    return;
  }

  // ================= phase1b branch: warp-per-b =================
  int w = tid >> 5, lane = tid & 31;
  int b = (blockIdx.x - PROTO_BLOCKS)*8 + w;

  float (*sDm)[MM][MM]   = (float(*)[MM][MM])(sBuf);               // 3200
  float (*sHS)[NNB][NNB] = (float(*)[NNB][NNB])(sBuf + 3200);      // 2592
  float (*sHn)[FIN]      = (float(*)[FIN])(sBuf + 5792);           // 4096
  float (*sVm)[NNB]      = (float(*)[NNB])(sBuf + 9888);           // 288
  unsigned (*sNbr)[MM]   = (unsigned(*)[MM])(sBuf + 10176);        // 320
  float (*sTnsT)[32]     = (float(*)[32])(sBuf + 10496);           // 1152
  float* sWn             = (float*)(sBuf + 11648);                 // 16384

  for (int u=tid; u<NNB*32; u+=256) sTnsT[u>>5][u&31] = g_tnsT[u];
  #pragma unroll
  for (int i=0;i<16;i++) sWn[tid + i*256] = wn_w1[tid + i*256];

  const float* HR = g_Hraw + (size_t)b*MM*GN;

  if (lane < MM){
    int idv = idxs[b*MM + lane];
    if (lane >= 1) sVm[w][lane-1] = (idv != NALL) ? 1.f : 0.f;
    unsigned nb=0;
    const float* arow = adj + (size_t)b*MM*MM + lane*MM;
    #pragma unroll
    for (int j=0;j<MM;j++) if (arow[j] > 1e-5f) nb |= (1u<<j);
    sNbr[w][lane]=nb;
  }
  __syncthreads();

  float vs = 0.f;
  #pragma unroll
  for (int j=0;j<NNB;j++) vs += sVm[w][j];
  float vsi = 1.f/(vs + 1e-9f);

  if (lane < MM){
    float drow[MM];
    #pragma unroll
    for (int j=0;j<MM;j++) drow[j] = (j==lane)?0.f:10.f;
    unsigned reach = 1u<<lane, frontier = 1u<<lane;
    for (int step=1; step<MM; step++){
      unsigned nxt=0;
      #pragma unroll
      for (int v=0;v<MM;v++) if (frontier & (1u<<v)) nxt |= sNbr[w][v];
      nxt &= ~reach;
      if (!nxt) break;
      #pragma unroll
      for (int v=0;v<MM;v++) if (nxt & (1u<<v)) drow[v]=(float)step;
      reach |= nxt; frontier = nxt;
    }
    #pragma unroll
    for (int j=0;j<MM;j++) sDm[w][lane][j]=drow[j];
  }
  __syncwarp();
  for (int q=lane; q<MM*MM; q+=32){
    int i=q/MM, j=q%MM;
    float fi = (i==0)?1.f:sVm[w][i-1];
    float fj = (j==0)?1.f:sVm[w][j-1];
    sDm[w][i][j] = (fi*fj>0.f) ? sDm[w][i][j]*0.1f : 1.0f;
  }
  __syncwarp();

  // ---- batched LN statistics ----
  float sv[MM], qv[MM];
  float a00, a01, a02, a03;
  #pragma unroll
  for (int r=0;r<MM;r++){
    const float* Hr = HR + r*GN;
    float a0=Hr[lane], a1=Hr[lane+32], a2=Hr[lane+64], a3=Hr[lane+96];
    sv[r] = (a0+a1)+(a2+a3);
    qv[r] = (a0*a0+a1*a1)+(a2*a2+a3*a3);
    if (r==0){ a00=a0; a01=a1; a02=a2; a03=a3; }
  }
  #pragma unroll
  for (int o=16;o;o>>=1){
    #pragma unroll
    for (int r=0;r<MM;r++){
      sv[r] += __shfl_xor_sync(0xffffffffu, sv[r], o);
      qv[r] += __shfl_xor_sync(0xffffffffu, qv[r], o);
    }
  }
  float muv[NNB], rsv[NNB];
  float mu0 = sv[0]*(1.f/FIN);
  float rs0 = rsqrtf(fmaxf(qv[0]*(1.f/FIN) - mu0*mu0, 0.f) + 1e-5f);
  #pragma unroll
  for (int r=1;r<MM;r++){
    float mu = sv[r]*(1.f/FIN);
    muv[r-1] = mu;
    rsv[r-1] = rsqrtf(fmaxf(qv[r]*(1.f/FIN) - mu*mu, 0.f) + 1e-5f);
  }
  {
    float lg0=lng[lane], lg1=lng[lane+32], lg2=lng[lane+64], lg3=lng[lane+96];
    float lb0=lnb[lane], lb1=lnb[lane+32], lb2=lnb[lane+64], lb3=lnb[lane+96];
    float h0=(a00-mu0)*rs0*lg0+lb0, h1=(a01-mu0)*rs0*lg1+lb1;
    float h2=(a02-mu0)*rs0*lg2+lb2, h3=(a03-mu0)*rs0*lg3+lb3;
    sHn[w][lane]=h0; sHn[w][lane+32]=h1; sHn[w][lane+64]=h2; sHn[w][lane+96]=h3;
    g_hroot[(size_t)b*DXX+lane]=h0; g_hroot[(size_t)b*DXX+lane+32]=h1;
    g_hroot[(size_t)b*DXX+lane+64]=h2; g_hroot[(size_t)b*DXX+lane+96]=h3;
    float qq = wredsum((h0*h0+h1*h1)+(h2*h2+h3*h3));
    if (lane==0) g_hrootsq[b]=qq;
  }
  __syncwarp();

  if (lane < NNB){
    float c[NNB];
    #pragma unroll
    for (int i=0;i<NNB;i++) c[i]=sDm[w][1+i][1+lane];
    sort9(c);
    #pragma unroll
    for (int i=0;i<NNB;i++) sHS[w][i][lane]=c[i];
  }
  __syncwarp();
  if (lane < NNB){
    float mu=0.f;
    #pragma unroll
    for (int j=0;j<NNB;j++) mu+=sHS[w][lane][j];
    mu *= (1.f/NNB);
    float var=0.f;
    #pragma unroll
    for (int j=0;j<NNB;j++){ float d=sHS[w][lane][j]-mu; var+=d*d; }
    var *= (1.f/NNB);
    float rstd=rsqrtf(var+1e-5f);
    #pragma unroll
    for (int j=0;j<NNB;j++) sHS[w][lane][j]=(sHS[w][lane][j]-mu)*rstd*sg[j]+sb[j];
  }
  __syncwarp();

  {
    float cSgl=g_cSg[lane], cCbl=g_cCb[lane];
    float vals[NNB]; int ord[NNB];
    #pragma unroll
    for (int m=0;m<NNB;m++)
      vals[m] = rsv[m]*(HR[(1+m)*GN+128+lane] - muv[m]*cSgl) + cCbl;
    argsort9(vals, ord);
    float t1=0.f;
    #pragma unroll
    for (int j=0;j<NNB;j++){
      int mo=ord[j];
      float wv = sVm[w][mo]*vsi;
      float pv = vals[mo];
      g_Afeat[(size_t)b*576 + j*LL + lane]       = -2.f*wv*pv;
      g_Afeat[(size_t)b*576 + 288 + j*LL + lane] = wv;
      t1 += wv*pv*pv;
    }
    t1 = wredsum(t1);
    if (lane==0) g_T1feat[b]=t1;
  }
  {
    float vals[NNB]; int ord[NNB];
    #pragma unroll
    for (int m=0;m<NNB;m++){
      float v2=0.f;
      #pragma unroll
      for (int j=0;j<NNB;j++) v2 += sHS[w][m][j]*sTnsT[j][lane];
      vals[m]=v2;
    }
    argsort9(vals, ord);
    float t1=0.f;
    #pragma unroll
    for (int j=0;j<NNB;j++){
      int mo=ord[j];
      float wv = sVm[w][mo]*vsi;
      float pv = vals[mo];
      g_Astr[(size_t)b*576 + j*LL + lane]       = -2.f*wv*pv;
      g_Astr[(size_t)b*576 + 288 + j*LL + lane] = wv;
      t1 += wv*pv*pv;
    }
    t1 = wredsum(t1);
    if (lane==0) g_T1str[b]=t1;
  }
  if (lane==0){
    float rb[NNB]; int ord[NNB];
    #pragma unroll
    for (int j=0;j<NNB;j++) rb[j]=sDm[w][0][1+j];
    argsort9(rb, ord);
    float S=0.f;
    #pragma unroll
    for (int j=0;j<NNB;j++){
      int mo=ord[j];
      float wv=sVm[w][mo]*vsi;
      float v=rb[mo];
      g_Arad[(size_t)b*18+j]   = -2.f*wv*v;
      g_Arad[(size_t)b*18+9+j] = wv;
      S += wv*v*v;
    }
    g_Srad[b]=S;
  }
  {
    float v0 = wn_b1[lane], v1=0.f, v2=0.f, v3=0.f;
    #pragma unroll 8
    for (int d=0; d<DXX; d+=4){
      v0 += sHn[w][d+0]*sWn[(d+0)*32+lane];
      v1 += sHn[w][d+1]*sWn[(d+1)*32+lane];
      v2 += sHn[w][d+2]*sWn[(d+2)*32+lane];
      v3 += sHn[w][d+3]*sWn[(d+3)*32+lane];
    }
    g_hb[(size_t)b*32+lane] = (v0+v1)+(v2+v3);
  }
  {
    float cSga=g_cSg[32+lane], cCba=g_cCb[32+lane];
    float s=0.f;
    #pragma unroll
    for (int m=0;m<NNB;m++){
      float av = rsv[m]*(HR[(1+m)*GN+160+lane] - muv[m]*cSga) + cCba;
      s += sVm[w][m]*av;
    }
    float hid = fmaxf(an_b1[lane] + s*vsi, 0.f);
    float vv = wredsum(hid*an_w2[lane]);
    if (lane==0)
      g_alpha[b] = 1.0f/(1.0f+expf(-(alpha_raw[0] + vv + an_b2[0])));
  }
}

// ------------------- kernel 3: register-tiled combine -------------------
__device__ __forceinline__ void p2_loadA(const float* Aptr, int b0, int c0,
                                         int strideA, float scale,
                                         float (*sA)[20], int tid){
  #pragma unroll
  for (int it=0; it<2; it++){
    int u = tid + it*128;
    int bb = u >> 4, cq = u & 15;
    float4 v = *(const float4*)&Aptr[(size_t)(b0+bb)*strideA + c0 + cq*4];
    int c = cq*4;
    sA[c+0][bb]=v.x*scale; sA[c+1][bb]=v.y*scale;
    sA[c+2][bb]=v.z*scale; sA[c+3][bb]=v.w*scale;
  }
}
__device__ __forceinline__ void p2_loadP(const float* Pptr, int c0,
                                         int strideP, float (*sP)[68], int tid){
  #pragma unroll
  for (int it=0; it<8; it++){
    int u = tid + it*128;
    int kk = u >> 4, cq = u & 15;
    float4 v = *(const float4*)&Pptr[(size_t)kk*strideP + c0 + cq*4];
    int c = cq*4;
    sP[c+0][kk]=v.x; sP[c+1][kk]=v.y; sP[c+2][kk]=v.z; sP[c+3][kk]=v.w;
  }
}
__device__ __forceinline__ void p2_compute(const float (*sA)[20], const float (*sP)[68],
                                           int bg, int kg, float* acc){
  #pragma unroll 8
  for (int c=0;c<64;c++){
    float2 a = *(const float2*)&sA[c][bg*2];
    float4 p = *(const float4*)&sP[c][kg*4];
    acc[0]+=a.x*p.x; acc[1]+=a.x*p.y; acc[2]+=a.x*p.z; acc[3]+=a.x*p.w;
    acc[4]+=a.y*p.x; acc[5]+=a.y*p.y; acc[6]+=a.y*p.z; acc[7]+=a.y*p.w;
  }
}

__global__ __launch_bounds__(128)
void k_phase2(const float* wn_w2, const float* wn_b2, const float* w_raw,
              const float* log_gamma, float* out)
{
  int tid = threadIdx.x;
  int bg = tid >> 4;
  int kg = tid & 15;
  int b0 = blockIdx.x * TB2;

  __shared__ __align__(16) float sA[64][20];
  __shared__ __align__(16) float sP[64][68];
  __shared__ float sHb[TB2][33];
  __shared__ float sHp[KK][33];
  __shared__ float sArad[TB2][19];
  __shared__ float sPrad[KK][19];
  __shared__ float sScB[TB2][5];
  __shared__ float sHpsq[KK];
  __shared__ float sW2[32];

  for (int idx=tid; idx<TB2*32; idx+=128){ int bb=idx>>5, j=idx&31; sHb[bb][j]=g_hb[(size_t)(b0+bb)*32+j]; }
  for (int idx=tid; idx<KK*32; idx+=128){ int kk=idx>>5, j=idx&31; sHp[kk][j]=g_hp[kk*32+j]; }
  for (int idx=tid; idx<TB2*18; idx+=128){ int bb=idx/18, j=idx%18; sArad[bb][j]=g_Arad[(size_t)(b0+bb)*18+j]; }
  for (int idx=tid; idx<KK*18; idx+=128){ int kk=idx/18, j=idx%18; sPrad[kk][j]=g_Prad[kk*18+j]; }
  for (int idx=tid; idx<TB2*5; idx+=128){
    int bb=idx/5, q=idx%5, bgl=b0+bb;
    float v;
    switch(q){
      case 0: v=g_T1feat[bgl]; break;
      case 1: v=g_T1str[bgl];  break;
      case 2: v=g_Srad[bgl];   break;
      case 3: v=g_hrootsq[bgl];break;
      default:v=g_alpha[bgl];
    }
    sScB[bb][q]=v;
  }
  if (tid < KK) sHpsq[tid]=g_hproto_sq[tid];
  if (tid < 32) sW2[tid]=wn_w2[tid];

  float accF[8], accS[8], accR[8];
  #pragma unroll
  for (int q=0;q<8;q++){ accF[q]=0.f; accS[q]=0.f; accR[q]=0.f; }

  for (int ch=0; ch<9; ch++){
    __syncthreads();
    p2_loadA(g_Afeat, b0, ch*64, 576, 1.f, sA, tid);
    p2_loadP(g_Pfeat, ch*64, 576, sP, tid);
    __syncthreads();
    p2_compute(sA, sP, bg, kg, accF);
  }
  for (int ch=0; ch<9; ch++){
    __syncthreads();
    p2_loadA(g_Astr, b0, ch*64, 576, 1.f, sA, tid);
    p2_loadP(g_Pstr, ch*64, 576, sP, tid);
    __syncthreads();
    p2_compute(sA, sP, bg, kg, accS);
  }
  for (int ch=0; ch<2; ch++){
    __syncthreads();
    p2_loadA(g_hroot, b0, ch*64, DXX, -2.f, sA, tid);
    p2_loadP(g_hproto_root, ch*64, DXX, sP, tid);
    __syncthreads();
    p2_compute(sA, sP, bg, kg, accR);
  }

  float accD[8];
  #pragma unroll
  for (int q=0;q<8;q++) accD[q]=0.f;
  #pragma unroll
  for (int j=0;j<18;j++){
    float a0=sArad[bg*2+0][j], a1=sArad[bg*2+1][j];
    float p0=sPrad[kg*4+0][j], p1=sPrad[kg*4+1][j], p2=sPrad[kg*4+2][j], p3=sPrad[kg*4+3][j];
    accD[0]+=a0*p0; accD[1]+=a0*p1; accD[2]+=a0*p2; accD[3]+=a0*p3;
    accD[4]+=a1*p0; accD[5]+=a1*p1; accD[6]+=a1*p2; accD[7]+=a1*p3;
  }

  float wlog[8];
  #pragma unroll
  for (int q=0;q<8;q++) wlog[q]=0.f;
  #pragma unroll 8
  for (int j=0;j<32;j++){
    float w2 = sW2[j];
    float b0v=sHb[bg*2+0][j], b1v=sHb[bg*2+1][j];
    float p0=sHp[kg*4+0][j], p1=sHp[kg*4+1][j], p2=sHp[kg*4+2][j], p3=sHp[kg*4+3][j];
    wlog[0]+=fmaxf(b0v+p0,0.f)*w2; wlog[1]+=fmaxf(b0v+p1,0.f)*w2;
    wlog[2]+=fmaxf(b0v+p2,0.f)*w2; wlog[3]+=fmaxf(b0v+p3,0.f)*w2;
    wlog[4]+=fmaxf(b1v+p0,0.f)*w2; wlog[5]+=fmaxf(b1v+p1,0.f)*w2;
    wlog[6]+=fmaxf(b1v+p2,0.f)*w2; wlog[7]+=fmaxf(b1v+p3,0.f)*w2;
  }

  float wraw = w_raw[0], wb2 = wn_b2[0];
  float gamma = expf(log_gamma[0]);

  #pragma unroll
  for (int i=0;i<2;i++){
    int bi = bg*2+i;
    float T1f=sScB[bi][0], T1s=sScB[bi][1], Sr=sScB[bi][2], hrsq=sScB[bi][3], al=sScB[bi][4];
    float res[4];
    #pragma unroll
    for (int j=0;j<4;j++){
      int q = i*4+j;
      int kk = kg*4+j;
      float wgt = 1.f/(1.f+expf(-(wraw + wlog[q] + wb2)));
      float drf = hrsq + sHpsq[kk] + accR[q];
      float swf = (T1f + accF[q])*(1.f/(float)LL);
      float sws = (T1s + accS[q])*(1.f/(float)LL);
      float rad = Sr + accD[q];
      float df = wgt*drf + (1.f-wgt)*swf;
      float ds = wgt*rad + (1.f-wgt)*sws;
      float dfgw = al*df + (1.f-al)*ds;
      res[j] = expf(-gamma*dfgw);
    }
    *(float4*)&out[(size_t)(b0+bi)*KK + kg*4] = make_float4(res[0],res[1],res[2],res[3]);
  }
}

// ------------------- launcher -------------------
extern "C" void kernel_launch(void* const* d_in, const int* in_sizes, int n_in,
                              void* d_out, int out_size)
{
  const float* adj        = (const float*)d_in[0];
  const float* features   = (const float*)d_in[1];
  const int*   idxs       = (const int*)  d_in[2];
  const float* x_lin_w    = (const float*)d_in[3];
  const float* x_lin_b    = (const float*)d_in[4];
  const float* x_ln_g     = (const float*)d_in[5];
  const float* x_ln_b     = (const float*)d_in[6];
  const float* s_ln_g     = (const float*)d_in[7];
  const float* s_ln_b     = (const float*)d_in[8];
  const float* theta_x    = (const float*)d_in[9];
  const float* theta_s    = (const float*)d_in[10];
  const float* alpha_raw  = (const float*)d_in[11];
  const float* an_w1      = (const float*)d_in[12];
  const float* an_b1      = (const float*)d_in[13];
  const float* an_w2      = (const float*)d_in[14];
  const float* an_b2      = (const float*)d_in[15];
  const float* wn_w1      = (const float*)d_in[16];
  const float* wn_b1      = (const float*)d_in[17];
  const float* wn_w2      = (const float*)d_in[18];
  const float* wn_b2      = (const float*)d_in[19];
  const float* w_raw      = (const float*)d_in[20];
  const float* proto_root = (const float*)d_in[21];
  const float* proto_neigh= (const float*)d_in[22];
  const float* proto_rad  = (const float*)d_in[23];
  const float* proto_dn   = (const float*)d_in[24];
  const float* log_gamma  = (const float*)d_in[25];
  float* out = (float*)d_out;

  cudaFuncSetAttribute(k_lin_mma, cudaFuncAttributeMaxDynamicSharedMemorySize, SMEM_LIN);

  k_tn<<<1,128>>>(theta_x, theta_s);                          // launch 0
  k_prep<<<41,256>>>(x_lin_w, x_lin_b, x_ln_g, x_ln_b, an_w1);// launch 1
  k_lin_mma<<<(BB*MM)/128, 512, SMEM_LIN>>>(features, idxs);  // launch 2
  k_fused<<<PROTO_BLOCKS + BB/8, 256>>>(adj, idxs, x_ln_g, x_ln_b, s_ln_g, s_ln_b,
                                        an_b1, an_w2, an_b2, wn_w1, wn_b1, alpha_raw,
                                        x_lin_w, x_lin_b, proto_root, proto_neigh,
                                        proto_rad, proto_dn); // launch 3 (profiled)
  k_phase2<<<BB/TB2,128>>>(wn_w2, wn_b2, w_raw, log_gamma, out); // launch 4
}